// round 1
// baseline (speedup 1.0000x reference)
#include <cuda_runtime.h>
#include <cstdint>

// Problem constants (fixed by the dataset).
#define NMAX 100000
#define EMAX 3200000

// Scratch (device globals: allocation inside kernel_launch is forbidden).
__device__ float g_deg[NMAX];
__device__ float g_norm[EMAX];
__device__ float g_bufA[NMAX * 64];  // layer features ping
__device__ float g_bufB[NMAX * 64];  // layer features pong
__device__ float g_t1[NMAX * 64];    // Tx1 scratch
__device__ float g_t2[NMAX * 64];    // propagate(Tx1) scratch

// ---------------------------------------------------------------------------
// Utility: vectorized zero
// ---------------------------------------------------------------------------
__global__ void zero_k(float4* p, int n4) {
    int i = blockIdx.x * blockDim.x + threadIdx.x;
    int stride = gridDim.x * blockDim.x;
    float4 z = {0.f, 0.f, 0.f, 0.f};
    for (; i < n4; i += stride) p[i] = z;
}

// ---------------------------------------------------------------------------
// Degree: deg[src[e]] += ea[e]
// ---------------------------------------------------------------------------
__global__ void deg_k(const int* __restrict__ src, const float* __restrict__ ea,
                      float* __restrict__ deg, int E) {
    int e = blockIdx.x * blockDim.x + threadIdx.x;
    if (e < E) atomicAdd(&deg[src[e]], ea[e]);
}

// ---------------------------------------------------------------------------
// norm[e] = -rsqrt(deg[src]) * ea * rsqrt(deg[dst])   (0 where deg==0)
// ---------------------------------------------------------------------------
__global__ void norm_k(const int* __restrict__ src, const int* __restrict__ dst,
                       const float* __restrict__ ea, const float* __restrict__ deg,
                       float* __restrict__ norm, int E) {
    int e = blockIdx.x * blockDim.x + threadIdx.x;
    if (e >= E) return;
    float ds = deg[src[e]];
    float dd = deg[dst[e]];
    float is = ds > 0.f ? rsqrtf(ds) : 0.f;
    float id = dd > 0.f ? rsqrtf(dd) : 0.f;
    norm[e] = -is * ea[e] * id;
}

// ---------------------------------------------------------------------------
// Propagate, C==1: out[dst] += norm * x[src]
// ---------------------------------------------------------------------------
__global__ void prop1_k(const float* __restrict__ x, const int* __restrict__ src,
                        const int* __restrict__ dst, const float* __restrict__ norm,
                        float* __restrict__ out, int E) {
    int e = blockIdx.x * blockDim.x + threadIdx.x;
    if (e >= E) return;
    atomicAdd(&out[dst[e]], norm[e] * x[src[e]]);
}

// ---------------------------------------------------------------------------
// Propagate, C multiple of 4: thread = (edge, 4-channel group).
// Gather is a coalesced float4; scatter is a vectorized red.global.add.v4.f32.
// ---------------------------------------------------------------------------
template <int C>
__global__ void propC_k(const float* __restrict__ x, const int* __restrict__ src,
                        const int* __restrict__ dst, const float* __restrict__ norm,
                        float* __restrict__ out, int E) {
    constexpr int G = C / 4;  // power of two (4, 8, 16)
    int tid = blockIdx.x * blockDim.x + threadIdx.x;
    int e = tid / G;
    int g = tid % G;
    if (e >= E) return;
    int s = src[e];
    int d = dst[e];
    float w = norm[e];
    const float4 v = *reinterpret_cast<const float4*>(x + (size_t)s * C + g * 4);
    float4 r;
    r.x = w * v.x; r.y = w * v.y; r.z = w * v.z; r.w = w * v.w;
    float* p = out + (size_t)d * C + g * 4;
    asm volatile("red.global.add.v4.f32 [%0], {%1, %2, %3, %4};"
                 :: "l"(p), "f"(r.x), "f"(r.y), "f"(r.z), "f"(r.w)
                 : "memory");
}

// ---------------------------------------------------------------------------
// Combine: out[i] = act( Tx0 @ W0 + Tx1 @ W1 + (2*T2p - Tx0) @ W2 )
// thread = (node, cout); W staged in smem (lanes on cout -> conflict-free).
// Feature loads broadcast within a warp (same node across cout lanes).
// ---------------------------------------------------------------------------
template <int CIN, int COUT, bool RELU>
__global__ void combine_k(const float* __restrict__ f0, const float* __restrict__ t1,
                          const float* __restrict__ t2, const float* __restrict__ W,
                          float* __restrict__ out, int n) {
    __shared__ float sW[3 * CIN * COUT];
    for (int i = threadIdx.x; i < 3 * CIN * COUT; i += blockDim.x) sW[i] = W[i];
    __syncthreads();

    int tid = blockIdx.x * blockDim.x + threadIdx.x;
    int node = tid / COUT;
    int co = tid % COUT;
    if (node >= n) return;

    const float* sW0 = sW;
    const float* sW1 = sW + CIN * COUT;
    const float* sW2 = sW + 2 * CIN * COUT;

    float acc = 0.f;
#pragma unroll
    for (int c = 0; c < CIN; c++) {
        float a = f0[(size_t)node * CIN + c];
        float b = t1[(size_t)node * CIN + c];
        float d = 2.f * t2[(size_t)node * CIN + c] - a;
        acc = fmaf(a, sW0[c * COUT + co], acc);
        acc = fmaf(b, sW1[c * COUT + co], acc);
        acc = fmaf(d, sW2[c * COUT + co], acc);
    }
    out[(size_t)node * COUT + co] = RELU ? fmaxf(acc, 0.f) : acc;
}

// ---------------------------------------------------------------------------
// Host-side helpers
// ---------------------------------------------------------------------------
static inline int cdiv(long long a, int b) { return (int)((a + b - 1) / b); }

static void zero_async(float* p, long long n_floats) {
    int n4 = (int)(n_floats / 4);
    int grid = cdiv(n4, 256);
    if (grid > 8192) grid = 8192;
    zero_k<<<grid, 256>>>(reinterpret_cast<float4*>(p), n4);
}

template <int C>
static void run_prop(const float* x, const int* src, const int* dst,
                     const float* norm, float* out, int N, int E) {
    zero_async(out, (long long)N * C);
    long long total = (long long)E * (C / 4);
    propC_k<C><<<cdiv(total, 256), 256>>>(x, src, dst, norm, out, E);
}

extern "C" void kernel_launch(void* const* d_in, const int* in_sizes, int n_in,
                              void* d_out, int out_size) {
    const float* x = (const float*)d_in[0];           // [N, 1]
    const int* edge_index = (const int*)d_in[1];      // [2, E]
    const float* ea = (const float*)d_in[2];          // [E]
    const float* W1 = (const float*)d_in[3];          // [3,1,16]
    const float* W2 = (const float*)d_in[4];          // [3,16,32]
    const float* W3 = (const float*)d_in[5];          // [3,32,64]
    const float* W4 = (const float*)d_in[6];          // [3,64,2]

    const int N = in_sizes[0];
    const int E = in_sizes[2];
    const int* src = edge_index;
    const int* dst = edge_index + E;

    float *deg, *norm, *bufA, *bufB, *t1, *t2;
    cudaGetSymbolAddress((void**)&deg, g_deg);
    cudaGetSymbolAddress((void**)&norm, g_norm);
    cudaGetSymbolAddress((void**)&bufA, g_bufA);
    cudaGetSymbolAddress((void**)&bufB, g_bufB);
    cudaGetSymbolAddress((void**)&t1, g_t1);
    cudaGetSymbolAddress((void**)&t2, g_t2);

    // ---- normalization coefficients ----
    zero_async(deg, N);
    deg_k<<<cdiv(E, 256), 256>>>(src, ea, deg, E);
    norm_k<<<cdiv(E, 256), 256>>>(src, dst, ea, deg, norm, E);

    // ---- layer 1: 1 -> 16, relu ----
    zero_async(t1, N);
    prop1_k<<<cdiv(E, 256), 256>>>(x, src, dst, norm, t1, E);
    zero_async(t2, N);
    prop1_k<<<cdiv(E, 256), 256>>>(t1, src, dst, norm, t2, E);
    combine_k<1, 16, true><<<cdiv((long long)N * 16, 256), 256>>>(x, t1, t2, W1, bufA, N);

    // ---- layer 2: 16 -> 32, relu ----
    run_prop<16>(bufA, src, dst, norm, t1, N, E);
    run_prop<16>(t1, src, dst, norm, t2, N, E);
    combine_k<16, 32, true><<<cdiv((long long)N * 32, 256), 256>>>(bufA, t1, t2, W2, bufB, N);

    // ---- layer 3: 32 -> 64, relu ----
    run_prop<32>(bufB, src, dst, norm, t1, N, E);
    run_prop<32>(t1, src, dst, norm, t2, N, E);
    combine_k<32, 64, true><<<cdiv((long long)N * 64, 256), 256>>>(bufB, t1, t2, W3, bufA, N);

    // ---- layer 4: 64 -> 2, no relu ----
    run_prop<64>(bufA, src, dst, norm, t1, N, E);
    run_prop<64>(t1, src, dst, norm, t2, N, E);
    combine_k<64, 2, false><<<cdiv((long long)N * 2, 256), 256>>>(
        bufA, t1, t2, W4, (float*)d_out, N);
}

// round 2
// speedup vs baseline: 1.1076x; 1.1076x over previous
#include <cuda_runtime.h>
#include <cstdint>

#define NMAX 100000
#define EMAX 3200000

// Scratch (device globals: allocation is forbidden).
__device__ float g_deg[NMAX];
__device__ int   g_cnt[NMAX];          // in-degree histogram
__device__ int   g_rs[NMAX + 1];       // CSR row starts (by dst)
__device__ int   g_cur[NMAX];          // scatter cursors
__device__ uint2 g_edges[EMAX];        // packed {src, norm} sorted by dst
__device__ float g_bufA[NMAX * 64];
__device__ float g_bufB[NMAX * 64];
__device__ float g_t1[NMAX * 64];
__device__ float g_t2[NMAX * 64];

static inline int cdiv(long long a, int b) { return (int)((a + b - 1) / b); }

// ---------------------------------------------------------------------------
// zero int/float arrays
// ---------------------------------------------------------------------------
__global__ void zero_i_k(int* p, int n) {
    int i = blockIdx.x * blockDim.x + threadIdx.x;
    if (i < n) p[i] = 0;
}
__global__ void zero_f_k(float* p, int n) {
    int i = blockIdx.x * blockDim.x + threadIdx.x;
    if (i < n) p[i] = 0.f;
}

// ---------------------------------------------------------------------------
// deg[src[e]] += ea[e];  cnt[dst[e]] += 1   (fused pass over edges)
// ---------------------------------------------------------------------------
__global__ void deg_hist_k(const int* __restrict__ src, const int* __restrict__ dst,
                           const float* __restrict__ ea,
                           float* __restrict__ deg, int* __restrict__ cnt, int E) {
    int e = blockIdx.x * blockDim.x + threadIdx.x;
    if (e >= E) return;
    atomicAdd(&deg[src[e]], ea[e]);
    atomicAdd(&cnt[dst[e]], 1);
}

// ---------------------------------------------------------------------------
// exclusive scan of cnt[0..n) -> rs, cur;  rs[n] = total. Single block.
// ---------------------------------------------------------------------------
__global__ void scan_k(const int* __restrict__ cnt, int* __restrict__ rs,
                       int* __restrict__ cur, int n) {
    __shared__ int ssum[1024];
    int tid = threadIdx.x;
    int chunk = (n + 1023) / 1024;
    int b = tid * chunk;
    int e = min(b + chunk, n);
    int s = 0;
    for (int i = b; i < e; i++) s += cnt[i];
    ssum[tid] = s;
    __syncthreads();
    // inclusive Hillis-Steele
    for (int off = 1; off < 1024; off <<= 1) {
        int v = ssum[tid];
        int add = (tid >= off) ? ssum[tid - off] : 0;
        __syncthreads();
        ssum[tid] = v + add;
        __syncthreads();
    }
    int run = ssum[tid] - s;  // exclusive prefix for this thread's chunk
    for (int i = b; i < e; i++) {
        rs[i] = run;
        cur[i] = run;
        run += cnt[i];
    }
    if (tid == 1023) rs[n] = ssum[1023];
}

// ---------------------------------------------------------------------------
// scatter: compute norm inline, place packed {src, norm} at cursor slot
// ---------------------------------------------------------------------------
__global__ void scatter_k(const int* __restrict__ src, const int* __restrict__ dst,
                          const float* __restrict__ ea, const float* __restrict__ deg,
                          int* __restrict__ cur, uint2* __restrict__ ed, int E) {
    int e = blockIdx.x * blockDim.x + threadIdx.x;
    if (e >= E) return;
    int s = src[e];
    int d = dst[e];
    float ds = deg[s];
    float dd = deg[d];
    float is = ds > 0.f ? rsqrtf(ds) : 0.f;
    float id = dd > 0.f ? rsqrtf(dd) : 0.f;
    float w = -is * ea[e] * id;
    int slot = atomicAdd(&cur[d], 1);
    ed[slot] = make_uint2((unsigned)s, __float_as_uint(w));
}

// ---------------------------------------------------------------------------
// CSR gather propagate, C == 1: warp per node, lanes over edges, shfl-reduce
// ---------------------------------------------------------------------------
__global__ void prop_csr_c1(const float* __restrict__ x, const uint2* __restrict__ ed,
                            const int* __restrict__ rs, float* __restrict__ out, int N) {
    int warp = (blockIdx.x * blockDim.x + threadIdx.x) >> 5;
    int lane = threadIdx.x & 31;
    if (warp >= N) return;
    int beg = rs[warp], end = rs[warp + 1];
    float acc = 0.f;
    for (int j = beg + lane; j < end; j += 32) {
        uint2 e = ed[j];
        acc += __uint_as_float(e.y) * __ldg(x + e.x);
    }
#pragma unroll
    for (int off = 16; off > 0; off >>= 1)
        acc += __shfl_down_sync(0xffffffffu, acc, off);
    if (lane == 0) out[warp] = acc;
}

// ---------------------------------------------------------------------------
// CSR gather propagate, C == 16: half-warp per node (lanes 0-15 / 16-31)
// ---------------------------------------------------------------------------
__global__ void prop_csr_c16(const float* __restrict__ x, const uint2* __restrict__ ed,
                             const int* __restrict__ rs, float* __restrict__ out, int N) {
    int warp = (blockIdx.x * blockDim.x + threadIdx.x) >> 5;
    int lane = threadIdx.x & 31;
    int node = warp * 2 + (lane >> 4);
    int sub = lane & 15;
    if (node >= N) return;
    int beg = rs[node], end = rs[node + 1];
    float acc = 0.f;
    int j = beg;
    for (; j + 4 <= end; j += 4) {
        uint2 e0 = ed[j], e1 = ed[j + 1], e2 = ed[j + 2], e3 = ed[j + 3];
        float v0 = x[(size_t)e0.x * 16 + sub];
        float v1 = x[(size_t)e1.x * 16 + sub];
        float v2 = x[(size_t)e2.x * 16 + sub];
        float v3 = x[(size_t)e3.x * 16 + sub];
        acc = fmaf(__uint_as_float(e0.y), v0, acc);
        acc = fmaf(__uint_as_float(e1.y), v1, acc);
        acc = fmaf(__uint_as_float(e2.y), v2, acc);
        acc = fmaf(__uint_as_float(e3.y), v3, acc);
    }
    for (; j < end; j++) {
        uint2 e = ed[j];
        acc = fmaf(__uint_as_float(e.y), x[(size_t)e.x * 16 + sub], acc);
    }
    out[(size_t)node * 16 + sub] = acc;
}

// ---------------------------------------------------------------------------
// CSR gather propagate, C == 32: warp per node, lane per channel
// ---------------------------------------------------------------------------
__global__ void prop_csr_c32(const float* __restrict__ x, const uint2* __restrict__ ed,
                             const int* __restrict__ rs, float* __restrict__ out, int N) {
    int warp = (blockIdx.x * blockDim.x + threadIdx.x) >> 5;
    int lane = threadIdx.x & 31;
    if (warp >= N) return;
    int beg = rs[warp], end = rs[warp + 1];
    float acc = 0.f;
    int j = beg;
    for (; j + 4 <= end; j += 4) {
        uint2 e0 = ed[j], e1 = ed[j + 1], e2 = ed[j + 2], e3 = ed[j + 3];
        float v0 = x[(size_t)e0.x * 32 + lane];
        float v1 = x[(size_t)e1.x * 32 + lane];
        float v2 = x[(size_t)e2.x * 32 + lane];
        float v3 = x[(size_t)e3.x * 32 + lane];
        acc = fmaf(__uint_as_float(e0.y), v0, acc);
        acc = fmaf(__uint_as_float(e1.y), v1, acc);
        acc = fmaf(__uint_as_float(e2.y), v2, acc);
        acc = fmaf(__uint_as_float(e3.y), v3, acc);
    }
    for (; j < end; j++) {
        uint2 e = ed[j];
        acc = fmaf(__uint_as_float(e.y), x[(size_t)e.x * 32 + lane], acc);
    }
    out[(size_t)warp * 32 + lane] = acc;
}

// ---------------------------------------------------------------------------
// CSR gather propagate, C == 64: warp per node, lane covers 2 channels (float2)
// ---------------------------------------------------------------------------
__global__ void prop_csr_c64(const float* __restrict__ x, const uint2* __restrict__ ed,
                             const int* __restrict__ rs, float* __restrict__ out, int N) {
    int warp = (blockIdx.x * blockDim.x + threadIdx.x) >> 5;
    int lane = threadIdx.x & 31;
    if (warp >= N) return;
    int beg = rs[warp], end = rs[warp + 1];
    float ax = 0.f, ay = 0.f;
    int j = beg;
    for (; j + 4 <= end; j += 4) {
        uint2 e0 = ed[j], e1 = ed[j + 1], e2 = ed[j + 2], e3 = ed[j + 3];
        float2 v0 = *reinterpret_cast<const float2*>(x + (size_t)e0.x * 64 + lane * 2);
        float2 v1 = *reinterpret_cast<const float2*>(x + (size_t)e1.x * 64 + lane * 2);
        float2 v2 = *reinterpret_cast<const float2*>(x + (size_t)e2.x * 64 + lane * 2);
        float2 v3 = *reinterpret_cast<const float2*>(x + (size_t)e3.x * 64 + lane * 2);
        float w0 = __uint_as_float(e0.y), w1 = __uint_as_float(e1.y);
        float w2 = __uint_as_float(e2.y), w3 = __uint_as_float(e3.y);
        ax = fmaf(w0, v0.x, ax); ay = fmaf(w0, v0.y, ay);
        ax = fmaf(w1, v1.x, ax); ay = fmaf(w1, v1.y, ay);
        ax = fmaf(w2, v2.x, ax); ay = fmaf(w2, v2.y, ay);
        ax = fmaf(w3, v3.x, ax); ay = fmaf(w3, v3.y, ay);
    }
    for (; j < end; j++) {
        uint2 e = ed[j];
        float2 v = *reinterpret_cast<const float2*>(x + (size_t)e.x * 64 + lane * 2);
        float w = __uint_as_float(e.y);
        ax = fmaf(w, v.x, ax); ay = fmaf(w, v.y, ay);
    }
    float2 r; r.x = ax; r.y = ay;
    *reinterpret_cast<float2*>(out + (size_t)warp * 64 + lane * 2) = r;
}

// ---------------------------------------------------------------------------
// Combine: out = act(Tx0@W0 + Tx1@W1 + (2*T2p - Tx0)@W2); W staged in smem.
// ---------------------------------------------------------------------------
template <int CIN, int COUT, bool RELU>
__global__ void combine_k(const float* __restrict__ f0, const float* __restrict__ t1,
                          const float* __restrict__ t2, const float* __restrict__ W,
                          float* __restrict__ out, int n) {
    __shared__ float sW[3 * CIN * COUT];
    for (int i = threadIdx.x; i < 3 * CIN * COUT; i += blockDim.x) sW[i] = W[i];
    __syncthreads();

    int tid = blockIdx.x * blockDim.x + threadIdx.x;
    int node = tid / COUT;
    int co = tid % COUT;
    if (node >= n) return;

    const float* sW0 = sW;
    const float* sW1 = sW + CIN * COUT;
    const float* sW2 = sW + 2 * CIN * COUT;

    float acc = 0.f;
#pragma unroll
    for (int c = 0; c < CIN; c++) {
        float a = f0[(size_t)node * CIN + c];
        float b = t1[(size_t)node * CIN + c];
        float d = 2.f * t2[(size_t)node * CIN + c] - a;
        acc = fmaf(a, sW0[c * COUT + co], acc);
        acc = fmaf(b, sW1[c * COUT + co], acc);
        acc = fmaf(d, sW2[c * COUT + co], acc);
    }
    out[(size_t)node * COUT + co] = RELU ? fmaxf(acc, 0.f) : acc;
}

extern "C" void kernel_launch(void* const* d_in, const int* in_sizes, int n_in,
                              void* d_out, int out_size) {
    const float* x = (const float*)d_in[0];
    const int* edge_index = (const int*)d_in[1];
    const float* ea = (const float*)d_in[2];
    const float* W1 = (const float*)d_in[3];
    const float* W2 = (const float*)d_in[4];
    const float* W3 = (const float*)d_in[5];
    const float* W4 = (const float*)d_in[6];

    const int N = in_sizes[0];
    const int E = in_sizes[2];
    const int* src = edge_index;
    const int* dst = edge_index + E;

    float *deg, *bufA, *bufB, *t1, *t2;
    int *cnt, *rs, *cur;
    uint2* edges;
    cudaGetSymbolAddress((void**)&deg, g_deg);
    cudaGetSymbolAddress((void**)&cnt, g_cnt);
    cudaGetSymbolAddress((void**)&rs, g_rs);
    cudaGetSymbolAddress((void**)&cur, g_cur);
    cudaGetSymbolAddress((void**)&edges, g_edges);
    cudaGetSymbolAddress((void**)&bufA, g_bufA);
    cudaGetSymbolAddress((void**)&bufB, g_bufB);
    cudaGetSymbolAddress((void**)&t1, g_t1);
    cudaGetSymbolAddress((void**)&t2, g_t2);

    // ---- build normalization + dst-sorted CSR ----
    zero_f_k<<<cdiv(N, 256), 256>>>(deg, N);
    zero_i_k<<<cdiv(N, 256), 256>>>(cnt, N);
    deg_hist_k<<<cdiv(E, 256), 256>>>(src, dst, ea, deg, cnt, E);
    scan_k<<<1, 1024>>>(cnt, rs, cur, N);
    scatter_k<<<cdiv(E, 256), 256>>>(src, dst, ea, deg, cur, edges, E);

    const int WPB = 256;  // threads per block for warp-per-node kernels
    int grid_n = cdiv((long long)N * 32, WPB);        // 1 warp / node
    int grid_n2 = cdiv((long long)cdiv(N, 2) * 32, WPB);  // 2 nodes / warp (C=16)

    // ---- layer 1: 1 -> 16, relu ----
    prop_csr_c1<<<grid_n, WPB>>>(x, edges, rs, t1, N);
    prop_csr_c1<<<grid_n, WPB>>>(t1, edges, rs, t2, N);
    combine_k<1, 16, true><<<cdiv((long long)N * 16, 256), 256>>>(x, t1, t2, W1, bufA, N);

    // ---- layer 2: 16 -> 32, relu ----
    prop_csr_c16<<<grid_n2, WPB>>>(bufA, edges, rs, t1, N);
    prop_csr_c16<<<grid_n2, WPB>>>(t1, edges, rs, t2, N);
    combine_k<16, 32, true><<<cdiv((long long)N * 32, 256), 256>>>(bufA, t1, t2, W2, bufB, N);

    // ---- layer 3: 32 -> 64, relu ----
    prop_csr_c32<<<grid_n, WPB>>>(bufB, edges, rs, t1, N);
    prop_csr_c32<<<grid_n, WPB>>>(t1, edges, rs, t2, N);
    combine_k<32, 64, true><<<cdiv((long long)N * 64, 256), 256>>>(bufB, t1, t2, W3, bufA, N);

    // ---- layer 4: 64 -> 2, no relu ----
    prop_csr_c64<<<grid_n, WPB>>>(bufA, edges, rs, t1, N);
    prop_csr_c64<<<grid_n, WPB>>>(t1, edges, rs, t2, N);
    combine_k<64, 2, false><<<cdiv((long long)N * 2, 256), 256>>>(
        bufA, t1, t2, W4, (float*)d_out, N);
}

// round 3
// speedup vs baseline: 1.7283x; 1.5604x over previous
#include <cuda_runtime.h>
#include <cstdint>

#define NMAX 100000
#define EMAX 3200000

// Scratch (device globals: allocation is forbidden).
__device__ float g_deg[NMAX];
__device__ int   g_cnt[NMAX];          // in-degree histogram
__device__ int   g_rs[NMAX + 1];       // CSR row starts (by dst)
__device__ int   g_cur[NMAX];          // scatter cursors
__device__ int   g_bsum[128];          // block sums for scan
__device__ uint2 g_edges[EMAX];        // packed {src, norm} sorted by dst
__device__ float g_bufA[NMAX * 64];
__device__ float g_bufB[NMAX * 64];
__device__ float g_t1[NMAX * 64];
__device__ float g_t2[NMAX * 64];

static inline int cdiv(long long a, int b) { return (int)((a + b - 1) / b); }

// ---------------------------------------------------------------------------
// zero helpers
// ---------------------------------------------------------------------------
__global__ void zero_i_k(int* p, int n) {
    int i = blockIdx.x * blockDim.x + threadIdx.x;
    if (i < n) p[i] = 0;
}
__global__ void zero_f_k(float* p, int n) {
    int i = blockIdx.x * blockDim.x + threadIdx.x;
    if (i < n) p[i] = 0.f;
}

// ---------------------------------------------------------------------------
// deg[src[e]] += ea[e];  cnt[dst[e]] += 1
// ---------------------------------------------------------------------------
__global__ void deg_hist_k(const int* __restrict__ src, const int* __restrict__ dst,
                           const float* __restrict__ ea,
                           float* __restrict__ deg, int* __restrict__ cnt, int E) {
    int e = blockIdx.x * blockDim.x + threadIdx.x;
    if (e >= E) return;
    atomicAdd(&deg[src[e]], ea[e]);
    atomicAdd(&cnt[dst[e]], 1);
}

// ---------------------------------------------------------------------------
// Parallel exclusive scan of cnt -> rs, cur.  3 phases, 1024 elems / block.
// ---------------------------------------------------------------------------
#define SCAN_TPB 256
#define SCAN_ELEMS 1024

__global__ void bsum_k(const int* __restrict__ cnt, int* __restrict__ bsum, int n) {
    int base = blockIdx.x * SCAN_ELEMS;
    int s = 0;
    for (int i = threadIdx.x; i < SCAN_ELEMS; i += SCAN_TPB) {
        int idx = base + i;
        s += (idx < n) ? cnt[idx] : 0;
    }
#pragma unroll
    for (int o = 16; o > 0; o >>= 1) s += __shfl_down_sync(0xffffffffu, s, o);
    __shared__ int ws[SCAN_TPB / 32];
    if ((threadIdx.x & 31) == 0) ws[threadIdx.x >> 5] = s;
    __syncthreads();
    if (threadIdx.x == 0) {
        int t = 0;
#pragma unroll
        for (int w = 0; w < SCAN_TPB / 32; w++) t += ws[w];
        bsum[blockIdx.x] = t;
    }
}

// scan <=128 block sums; writes exclusive prefixes in-place, total to *total
__global__ void bscan_k(int* __restrict__ bsum, int nb, int* __restrict__ total) {
    __shared__ int sm[128];
    int v = (threadIdx.x < nb) ? bsum[threadIdx.x] : 0;
    sm[threadIdx.x] = v;
    __syncthreads();
    for (int o = 1; o < 128; o <<= 1) {
        int t = sm[threadIdx.x];
        int add = (threadIdx.x >= (unsigned)o) ? sm[threadIdx.x - o] : 0;
        __syncthreads();
        sm[threadIdx.x] = t + add;
        __syncthreads();
    }
    if (threadIdx.x < nb) bsum[threadIdx.x] = sm[threadIdx.x] - v;  // exclusive
    if (threadIdx.x == 127) *total = sm[127];
}

__global__ void expand_k(const int* __restrict__ cnt, const int* __restrict__ bsum,
                         int* __restrict__ rs, int* __restrict__ cur, int n) {
    int base = blockIdx.x * SCAN_ELEMS + threadIdx.x * 4;
    int c0 = 0, c1 = 0, c2 = 0, c3 = 0;
    if (base + 3 < n) {
        int4 v = *reinterpret_cast<const int4*>(cnt + base);
        c0 = v.x; c1 = v.y; c2 = v.z; c3 = v.w;
    } else {
        if (base + 0 < n) c0 = cnt[base + 0];
        if (base + 1 < n) c1 = cnt[base + 1];
        if (base + 2 < n) c2 = cnt[base + 2];
        if (base + 3 < n) c3 = cnt[base + 3];
    }
    int ts = c0 + c1 + c2 + c3;
    int lane = threadIdx.x & 31, wid = threadIdx.x >> 5;
    int inc = ts;
#pragma unroll
    for (int o = 1; o < 32; o <<= 1) {
        int v = __shfl_up_sync(0xffffffffu, inc, o);
        if (lane >= o) inc += v;
    }
    __shared__ int wsum[SCAN_TPB / 32];
    __shared__ int woff[SCAN_TPB / 32];
    if (lane == 31) wsum[wid] = inc;
    __syncthreads();
    if (threadIdx.x == 0) {
        int r = 0;
#pragma unroll
        for (int w = 0; w < SCAN_TPB / 32; w++) { woff[w] = r; r += wsum[w]; }
    }
    __syncthreads();
    int r = (inc - ts) + woff[wid] + bsum[blockIdx.x];
    if (base + 0 < n) { rs[base + 0] = r; cur[base + 0] = r; r += c0; }
    if (base + 1 < n) { rs[base + 1] = r; cur[base + 1] = r; r += c1; }
    if (base + 2 < n) { rs[base + 2] = r; cur[base + 2] = r; r += c2; }
    if (base + 3 < n) { rs[base + 3] = r; cur[base + 3] = r; r += c3; }
}

// ---------------------------------------------------------------------------
// scatter: compute norm inline, place packed {src, norm} at cursor slot
// ---------------------------------------------------------------------------
__global__ void scatter_k(const int* __restrict__ src, const int* __restrict__ dst,
                          const float* __restrict__ ea, const float* __restrict__ deg,
                          int* __restrict__ cur, uint2* __restrict__ ed, int E) {
    int e = blockIdx.x * blockDim.x + threadIdx.x;
    if (e >= E) return;
    int s = src[e];
    int d = dst[e];
    float ds = deg[s];
    float dd = deg[d];
    float is = ds > 0.f ? rsqrtf(ds) : 0.f;
    float id = dd > 0.f ? rsqrtf(dd) : 0.f;
    float w = -is * ea[e] * id;
    int slot = atomicAdd(&cur[d], 1);
    ed[slot] = make_uint2((unsigned)s, __float_as_uint(w));
}

// ---------------------------------------------------------------------------
// CSR gather propagate, C == 1: warp per node, lanes over edges, shfl-reduce
// ---------------------------------------------------------------------------
__global__ void prop_csr_c1(const float* __restrict__ x, const uint2* __restrict__ ed,
                            const int* __restrict__ rs, float* __restrict__ out, int N) {
    int warp = (blockIdx.x * blockDim.x + threadIdx.x) >> 5;
    int lane = threadIdx.x & 31;
    if (warp >= N) return;
    int beg = rs[warp], end = rs[warp + 1];
    float acc = 0.f;
    for (int j = beg + lane; j < end; j += 32) {
        uint2 e = ed[j];
        acc += __uint_as_float(e.y) * __ldg(x + e.x);
    }
#pragma unroll
    for (int off = 16; off > 0; off >>= 1)
        acc += __shfl_down_sync(0xffffffffu, acc, off);
    if (lane == 0) out[warp] = acc;
}

// ---------------------------------------------------------------------------
// CSR gather propagate, C == 16: half-warp per node, unroll-8 batched loads
// ---------------------------------------------------------------------------
__global__ void prop_csr_c16(const float* __restrict__ x, const uint2* __restrict__ ed,
                             const int* __restrict__ rs, float* __restrict__ out, int N) {
    int warp = (blockIdx.x * blockDim.x + threadIdx.x) >> 5;
    int lane = threadIdx.x & 31;
    int node = warp * 2 + (lane >> 4);
    int sub = lane & 15;
    if (node >= N) return;
    int beg = rs[node], end = rs[node + 1];
    float acc = 0.f;
    int j = beg;
    for (; j + 8 <= end; j += 8) {
        uint2 e[8];
#pragma unroll
        for (int k = 0; k < 8; k++) e[k] = ed[j + k];
        float v[8];
#pragma unroll
        for (int k = 0; k < 8; k++) v[k] = __ldg(x + (size_t)e[k].x * 16 + sub);
#pragma unroll
        for (int k = 0; k < 8; k++) acc = fmaf(__uint_as_float(e[k].y), v[k], acc);
    }
    for (; j < end; j++) {
        uint2 e = ed[j];
        acc = fmaf(__uint_as_float(e.y), __ldg(x + (size_t)e.x * 16 + sub), acc);
    }
    out[(size_t)node * 16 + sub] = acc;
}

// ---------------------------------------------------------------------------
// CSR gather propagate, C == 32: warp per node, unroll-8 batched loads
// ---------------------------------------------------------------------------
__global__ void prop_csr_c32(const float* __restrict__ x, const uint2* __restrict__ ed,
                             const int* __restrict__ rs, float* __restrict__ out, int N) {
    int warp = (blockIdx.x * blockDim.x + threadIdx.x) >> 5;
    int lane = threadIdx.x & 31;
    if (warp >= N) return;
    int beg = rs[warp], end = rs[warp + 1];
    const float* xr = x + lane;
    float acc = 0.f;
    int j = beg;
    for (; j + 8 <= end; j += 8) {
        uint2 e[8];
#pragma unroll
        for (int k = 0; k < 8; k++) e[k] = ed[j + k];
        float v[8];
#pragma unroll
        for (int k = 0; k < 8; k++) v[k] = __ldg(xr + (size_t)e[k].x * 32);
#pragma unroll
        for (int k = 0; k < 8; k++) acc = fmaf(__uint_as_float(e[k].y), v[k], acc);
    }
    for (; j < end; j++) {
        uint2 e = ed[j];
        acc = fmaf(__uint_as_float(e.y), __ldg(xr + (size_t)e.x * 32), acc);
    }
    out[(size_t)warp * 32 + lane] = acc;
}

// ---------------------------------------------------------------------------
// CSR gather propagate, C == 64: warp per node, float2/lane, unroll-8
// ---------------------------------------------------------------------------
__global__ void prop_csr_c64(const float* __restrict__ x, const uint2* __restrict__ ed,
                             const int* __restrict__ rs, float* __restrict__ out, int N) {
    int warp = (blockIdx.x * blockDim.x + threadIdx.x) >> 5;
    int lane = threadIdx.x & 31;
    if (warp >= N) return;
    int beg = rs[warp], end = rs[warp + 1];
    const float* xr = x + lane * 2;
    float ax = 0.f, ay = 0.f;
    int j = beg;
    for (; j + 8 <= end; j += 8) {
        uint2 e[8];
#pragma unroll
        for (int k = 0; k < 8; k++) e[k] = ed[j + k];
        float2 v[8];
#pragma unroll
        for (int k = 0; k < 8; k++)
            v[k] = *reinterpret_cast<const float2*>(xr + (size_t)e[k].x * 64);
#pragma unroll
        for (int k = 0; k < 8; k++) {
            float w = __uint_as_float(e[k].y);
            ax = fmaf(w, v[k].x, ax);
            ay = fmaf(w, v[k].y, ay);
        }
    }
    for (; j < end; j++) {
        uint2 e = ed[j];
        float2 v = *reinterpret_cast<const float2*>(xr + (size_t)e.x * 64);
        float w = __uint_as_float(e.y);
        ax = fmaf(w, v.x, ax);
        ay = fmaf(w, v.y, ay);
    }
    float2 r; r.x = ax; r.y = ay;
    *reinterpret_cast<float2*>(out + (size_t)warp * 64 + lane * 2) = r;
}

// ---------------------------------------------------------------------------
// Combine 1->16 (thread = node*16+co; features broadcast within warp)
// ---------------------------------------------------------------------------
__global__ void combine_1_16(const float* __restrict__ f0, const float* __restrict__ t1,
                             const float* __restrict__ t2, const float* __restrict__ W,
                             float* __restrict__ out, int n) {
    __shared__ float sW[48];
    if (threadIdx.x < 48) sW[threadIdx.x] = W[threadIdx.x];
    __syncthreads();
    int tid = blockIdx.x * blockDim.x + threadIdx.x;
    int node = tid >> 4;
    int co = tid & 15;
    if (node >= n) return;
    float a = f0[node];
    float b = t1[node];
    float d = 2.f * t2[node] - a;
    float acc = a * sW[co] + b * sW[16 + co] + d * sW[32 + co];
    out[(size_t)node * 16 + co] = fmaxf(acc, 0.f);
}

// ---------------------------------------------------------------------------
// Combine 16->32: warp per node; lane holds feature c=lane&15, shfl broadcast
// ---------------------------------------------------------------------------
__global__ void combine_16_32(const float* __restrict__ f0, const float* __restrict__ t1,
                              const float* __restrict__ t2, const float* __restrict__ W,
                              float* __restrict__ out, int n) {
    __shared__ float sW[3 * 16 * 32];
    for (int i = threadIdx.x; i < 3 * 16 * 32; i += blockDim.x) sW[i] = W[i];
    __syncthreads();
    int warp = (blockIdx.x * blockDim.x + threadIdx.x) >> 5;
    int lane = threadIdx.x & 31;
    if (warp >= n) return;
    int c = lane & 15;
    float a = f0[(size_t)warp * 16 + c];
    float b = t1[(size_t)warp * 16 + c];
    float d = 2.f * t2[(size_t)warp * 16 + c] - a;
    float acc = 0.f;
#pragma unroll
    for (int cc = 0; cc < 16; cc++) {
        float av = __shfl_sync(0xffffffffu, a, cc);
        float bv = __shfl_sync(0xffffffffu, b, cc);
        float dv = __shfl_sync(0xffffffffu, d, cc);
        acc = fmaf(av, sW[cc * 32 + lane], acc);
        acc = fmaf(bv, sW[512 + cc * 32 + lane], acc);
        acc = fmaf(dv, sW[1024 + cc * 32 + lane], acc);
    }
    out[(size_t)warp * 32 + lane] = fmaxf(acc, 0.f);
}

// ---------------------------------------------------------------------------
// Combine 32->64: warp per node; lane holds feature c=lane; 2 couts per lane
// ---------------------------------------------------------------------------
__global__ void combine_32_64(const float* __restrict__ f0, const float* __restrict__ t1,
                              const float* __restrict__ t2, const float* __restrict__ W,
                              float* __restrict__ out, int n) {
    __shared__ float sW[3 * 32 * 64];
    for (int i = threadIdx.x; i < 3 * 32 * 64; i += blockDim.x) sW[i] = W[i];
    __syncthreads();
    int warp = (blockIdx.x * blockDim.x + threadIdx.x) >> 5;
    int lane = threadIdx.x & 31;
    if (warp >= n) return;
    float a = f0[(size_t)warp * 32 + lane];
    float b = t1[(size_t)warp * 32 + lane];
    float d = 2.f * t2[(size_t)warp * 32 + lane] - a;
    float acc0 = 0.f, acc1 = 0.f;
#pragma unroll
    for (int cc = 0; cc < 32; cc++) {
        float av = __shfl_sync(0xffffffffu, a, cc);
        float bv = __shfl_sync(0xffffffffu, b, cc);
        float dv = __shfl_sync(0xffffffffu, d, cc);
        const float* w0 = sW + cc * 64;
        const float* w1 = sW + 2048 + cc * 64;
        const float* w2 = sW + 4096 + cc * 64;
        acc0 = fmaf(av, w0[lane], acc0);
        acc0 = fmaf(bv, w1[lane], acc0);
        acc0 = fmaf(dv, w2[lane], acc0);
        acc1 = fmaf(av, w0[lane + 32], acc1);
        acc1 = fmaf(bv, w1[lane + 32], acc1);
        acc1 = fmaf(dv, w2[lane + 32], acc1);
    }
    out[(size_t)warp * 64 + lane] = fmaxf(acc0, 0.f);
    out[(size_t)warp * 64 + lane + 32] = fmaxf(acc1, 0.f);
}

// ---------------------------------------------------------------------------
// Combine 64->2: warp per node; coalesced feature loads; warp reduction
// ---------------------------------------------------------------------------
__global__ void combine_64_2(const float* __restrict__ f0, const float* __restrict__ t1,
                             const float* __restrict__ t2, const float* __restrict__ W,
                             float* __restrict__ out, int n) {
    __shared__ float sW[3 * 64 * 2];
    for (int i = threadIdx.x; i < 3 * 64 * 2; i += blockDim.x) sW[i] = W[i];
    __syncthreads();
    int warp = (blockIdx.x * blockDim.x + threadIdx.x) >> 5;
    int lane = threadIdx.x & 31;
    if (warp >= n) return;
    size_t base = (size_t)warp * 64;
    float a0 = f0[base + lane],      a1 = f0[base + lane + 32];
    float b0 = t1[base + lane],      b1 = t1[base + lane + 32];
    float d0 = 2.f * t2[base + lane] - a0;
    float d1 = 2.f * t2[base + lane + 32] - a1;
    int c0 = lane, c1 = lane + 32;
    float acc0 = a0 * sW[c0 * 2] + b0 * sW[128 + c0 * 2] + d0 * sW[256 + c0 * 2]
               + a1 * sW[c1 * 2] + b1 * sW[128 + c1 * 2] + d1 * sW[256 + c1 * 2];
    float acc1 = a0 * sW[c0 * 2 + 1] + b0 * sW[128 + c0 * 2 + 1] + d0 * sW[256 + c0 * 2 + 1]
               + a1 * sW[c1 * 2 + 1] + b1 * sW[128 + c1 * 2 + 1] + d1 * sW[256 + c1 * 2 + 1];
#pragma unroll
    for (int off = 16; off > 0; off >>= 1) {
        acc0 += __shfl_down_sync(0xffffffffu, acc0, off);
        acc1 += __shfl_down_sync(0xffffffffu, acc1, off);
    }
    if (lane == 0) {
        out[(size_t)warp * 2] = acc0;
        out[(size_t)warp * 2 + 1] = acc1;
    }
}

extern "C" void kernel_launch(void* const* d_in, const int* in_sizes, int n_in,
                              void* d_out, int out_size) {
    const float* x = (const float*)d_in[0];
    const int* edge_index = (const int*)d_in[1];
    const float* ea = (const float*)d_in[2];
    const float* W1 = (const float*)d_in[3];
    const float* W2 = (const float*)d_in[4];
    const float* W3 = (const float*)d_in[5];
    const float* W4 = (const float*)d_in[6];

    const int N = in_sizes[0];
    const int E = in_sizes[2];
    const int* src = edge_index;
    const int* dst = edge_index + E;

    float *deg, *bufA, *bufB, *t1, *t2;
    int *cnt, *rs, *cur, *bsum;
    uint2* edges;
    cudaGetSymbolAddress((void**)&deg, g_deg);
    cudaGetSymbolAddress((void**)&cnt, g_cnt);
    cudaGetSymbolAddress((void**)&rs, g_rs);
    cudaGetSymbolAddress((void**)&cur, g_cur);
    cudaGetSymbolAddress((void**)&bsum, g_bsum);
    cudaGetSymbolAddress((void**)&edges, g_edges);
    cudaGetSymbolAddress((void**)&bufA, g_bufA);
    cudaGetSymbolAddress((void**)&bufB, g_bufB);
    cudaGetSymbolAddress((void**)&t1, g_t1);
    cudaGetSymbolAddress((void**)&t2, g_t2);

    // ---- build normalization + dst-sorted CSR ----
    zero_f_k<<<cdiv(N, 256), 256>>>(deg, N);
    zero_i_k<<<cdiv(N, 256), 256>>>(cnt, N);
    deg_hist_k<<<cdiv(E, 256), 256>>>(src, dst, ea, deg, cnt, E);
    int nb = cdiv(N, SCAN_ELEMS);
    bsum_k<<<nb, SCAN_TPB>>>(cnt, bsum, N);
    bscan_k<<<1, 128>>>(bsum, nb, rs + N);  // rs[N] = E
    expand_k<<<nb, SCAN_TPB>>>(cnt, bsum, rs, cur, N);
    scatter_k<<<cdiv(E, 256), 256>>>(src, dst, ea, deg, cur, edges, E);

    const int WPB = 256;
    int grid_n = cdiv((long long)N * 32, WPB);
    int grid_n2 = cdiv((long long)cdiv(N, 2) * 32, WPB);

    // ---- layer 1: 1 -> 16, relu ----
    prop_csr_c1<<<grid_n, WPB>>>(x, edges, rs, t1, N);
    prop_csr_c1<<<grid_n, WPB>>>(t1, edges, rs, t2, N);
    combine_1_16<<<cdiv((long long)N * 16, 256), 256>>>(x, t1, t2, W1, bufA, N);

    // ---- layer 2: 16 -> 32, relu ----
    prop_csr_c16<<<grid_n2, WPB>>>(bufA, edges, rs, t1, N);
    prop_csr_c16<<<grid_n2, WPB>>>(t1, edges, rs, t2, N);
    combine_16_32<<<grid_n, WPB>>>(bufA, t1, t2, W2, bufB, N);

    // ---- layer 3: 32 -> 64, relu ----
    prop_csr_c32<<<grid_n, WPB>>>(bufB, edges, rs, t1, N);
    prop_csr_c32<<<grid_n, WPB>>>(t1, edges, rs, t2, N);
    combine_32_64<<<grid_n, WPB>>>(bufB, t1, t2, W3, bufA, N);

    // ---- layer 4: 64 -> 2, no relu ----
    prop_csr_c64<<<grid_n, WPB>>>(bufA, edges, rs, t1, N);
    prop_csr_c64<<<grid_n, WPB>>>(t1, edges, rs, t2, N);
    combine_64_2<<<grid_n, WPB>>>(bufA, t1, t2, W4, (float*)d_out, N);
}

// round 4
// speedup vs baseline: 1.9790x; 1.1450x over previous
#include <cuda_runtime.h>
#include <cstdint>

#define NMAX 100000
#define EMAX 3200000

// Scratch (device globals: allocation is forbidden).
__device__ float g_deg[NMAX];
__device__ int   g_cnt[NMAX];          // in-degree histogram
__device__ int   g_rs[NMAX + 1];       // CSR row starts (by dst)
__device__ int   g_cur[NMAX];          // scatter cursors
__device__ int   g_bsum[128];          // block sums for scan
__device__ uint2 g_edges[EMAX];        // packed {src, norm} sorted by dst
__device__ float g_bufA[NMAX * 64];
__device__ float g_bufB[NMAX * 64];
__device__ float g_t1[NMAX * 64];
__device__ float g_t2[NMAX * 64];

static inline int cdiv(long long a, int b) { return (int)((a + b - 1) / b); }

// ---------------------------------------------------------------------------
// zero helpers
// ---------------------------------------------------------------------------
__global__ void zero_i_k(int* p, int n) {
    int i = blockIdx.x * blockDim.x + threadIdx.x;
    if (i < n) p[i] = 0;
}
__global__ void zero_f_k(float* p, int n) {
    int i = blockIdx.x * blockDim.x + threadIdx.x;
    if (i < n) p[i] = 0.f;
}

// ---------------------------------------------------------------------------
// deg[src[e]] += ea[e];  cnt[dst[e]] += 1
// ---------------------------------------------------------------------------
__global__ void deg_hist_k(const int* __restrict__ src, const int* __restrict__ dst,
                           const float* __restrict__ ea,
                           float* __restrict__ deg, int* __restrict__ cnt, int E) {
    int e = blockIdx.x * blockDim.x + threadIdx.x;
    if (e >= E) return;
    atomicAdd(&deg[src[e]], ea[e]);
    atomicAdd(&cnt[dst[e]], 1);
}

// ---------------------------------------------------------------------------
// Parallel exclusive scan of cnt -> rs, cur.  3 phases, 1024 elems / block.
// ---------------------------------------------------------------------------
#define SCAN_TPB 256
#define SCAN_ELEMS 1024

__global__ void bsum_k(const int* __restrict__ cnt, int* __restrict__ bsum, int n) {
    int base = blockIdx.x * SCAN_ELEMS;
    int s = 0;
    for (int i = threadIdx.x; i < SCAN_ELEMS; i += SCAN_TPB) {
        int idx = base + i;
        s += (idx < n) ? cnt[idx] : 0;
    }
#pragma unroll
    for (int o = 16; o > 0; o >>= 1) s += __shfl_down_sync(0xffffffffu, s, o);
    __shared__ int ws[SCAN_TPB / 32];
    if ((threadIdx.x & 31) == 0) ws[threadIdx.x >> 5] = s;
    __syncthreads();
    if (threadIdx.x == 0) {
        int t = 0;
#pragma unroll
        for (int w = 0; w < SCAN_TPB / 32; w++) t += ws[w];
        bsum[blockIdx.x] = t;
    }
}

__global__ void bscan_k(int* __restrict__ bsum, int nb, int* __restrict__ total) {
    __shared__ int sm[128];
    int v = (threadIdx.x < nb) ? bsum[threadIdx.x] : 0;
    sm[threadIdx.x] = v;
    __syncthreads();
    for (int o = 1; o < 128; o <<= 1) {
        int t = sm[threadIdx.x];
        int add = (threadIdx.x >= (unsigned)o) ? sm[threadIdx.x - o] : 0;
        __syncthreads();
        sm[threadIdx.x] = t + add;
        __syncthreads();
    }
    if (threadIdx.x < nb) bsum[threadIdx.x] = sm[threadIdx.x] - v;  // exclusive
    if (threadIdx.x == 127) *total = sm[127];
}

__global__ void expand_k(const int* __restrict__ cnt, const int* __restrict__ bsum,
                         int* __restrict__ rs, int* __restrict__ cur, int n) {
    int base = blockIdx.x * SCAN_ELEMS + threadIdx.x * 4;
    int c0 = 0, c1 = 0, c2 = 0, c3 = 0;
    if (base + 3 < n) {
        int4 v = *reinterpret_cast<const int4*>(cnt + base);
        c0 = v.x; c1 = v.y; c2 = v.z; c3 = v.w;
    } else {
        if (base + 0 < n) c0 = cnt[base + 0];
        if (base + 1 < n) c1 = cnt[base + 1];
        if (base + 2 < n) c2 = cnt[base + 2];
        if (base + 3 < n) c3 = cnt[base + 3];
    }
    int ts = c0 + c1 + c2 + c3;
    int lane = threadIdx.x & 31, wid = threadIdx.x >> 5;
    int inc = ts;
#pragma unroll
    for (int o = 1; o < 32; o <<= 1) {
        int v = __shfl_up_sync(0xffffffffu, inc, o);
        if (lane >= o) inc += v;
    }
    __shared__ int wsum[SCAN_TPB / 32];
    __shared__ int woff[SCAN_TPB / 32];
    if (lane == 31) wsum[wid] = inc;
    __syncthreads();
    if (threadIdx.x == 0) {
        int r = 0;
#pragma unroll
        for (int w = 0; w < SCAN_TPB / 32; w++) { woff[w] = r; r += wsum[w]; }
    }
    __syncthreads();
    int r = (inc - ts) + woff[wid] + bsum[blockIdx.x];
    if (base + 0 < n) { rs[base + 0] = r; cur[base + 0] = r; r += c0; }
    if (base + 1 < n) { rs[base + 1] = r; cur[base + 1] = r; r += c1; }
    if (base + 2 < n) { rs[base + 2] = r; cur[base + 2] = r; r += c2; }
    if (base + 3 < n) { rs[base + 3] = r; cur[base + 3] = r; r += c3; }
}

// ---------------------------------------------------------------------------
// scatter: compute norm inline, place packed {src, norm} at cursor slot
// ---------------------------------------------------------------------------
__global__ void scatter_k(const int* __restrict__ src, const int* __restrict__ dst,
                          const float* __restrict__ ea, const float* __restrict__ deg,
                          int* __restrict__ cur, uint2* __restrict__ ed, int E) {
    int e = blockIdx.x * blockDim.x + threadIdx.x;
    if (e >= E) return;
    int s = src[e];
    int d = dst[e];
    float ds = deg[s];
    float dd = deg[d];
    float is = ds > 0.f ? rsqrtf(ds) : 0.f;
    float id = dd > 0.f ? rsqrtf(dd) : 0.f;
    float w = -is * ea[e] * id;
    int slot = atomicAdd(&cur[d], 1);
    ed[slot] = make_uint2((unsigned)s, __float_as_uint(w));
}

// ---------------------------------------------------------------------------
// CSR gather propagate, C == 1: warp per node, lanes over edges, shfl-reduce
// ---------------------------------------------------------------------------
__global__ void prop_csr_c1(const float* __restrict__ x, const uint2* __restrict__ ed,
                            const int* __restrict__ rs, float* __restrict__ out, int N) {
    int warp = (blockIdx.x * blockDim.x + threadIdx.x) >> 5;
    int lane = threadIdx.x & 31;
    if (warp >= N) return;
    int beg = rs[warp], end = rs[warp + 1];
    float acc = 0.f;
    for (int j = beg + lane; j < end; j += 32) {
        uint2 e = ed[j];
        acc += __uint_as_float(e.y) * __ldg(x + e.x);
    }
#pragma unroll
    for (int off = 16; off > 0; off >>= 1)
        acc += __shfl_down_sync(0xffffffffu, acc, off);
    if (lane == 0) out[warp] = acc;
}

// ---------------------------------------------------------------------------
// CSR gather propagate, C == 16: half-warp per node, unroll-8 batched loads
// ---------------------------------------------------------------------------
__global__ void prop_csr_c16(const float* __restrict__ x, const uint2* __restrict__ ed,
                             const int* __restrict__ rs, float* __restrict__ out, int N) {
    int warp = (blockIdx.x * blockDim.x + threadIdx.x) >> 5;
    int lane = threadIdx.x & 31;
    int node = warp * 2 + (lane >> 4);
    int sub = lane & 15;
    if (node >= N) return;
    int beg = rs[node], end = rs[node + 1];
    float acc = 0.f;
    int j = beg;
    for (; j + 8 <= end; j += 8) {
        uint2 e[8];
#pragma unroll
        for (int k = 0; k < 8; k++) e[k] = ed[j + k];
        float v[8];
#pragma unroll
        for (int k = 0; k < 8; k++) v[k] = __ldg(x + (size_t)e[k].x * 16 + sub);
#pragma unroll
        for (int k = 0; k < 8; k++) acc = fmaf(__uint_as_float(e[k].y), v[k], acc);
    }
    for (; j < end; j++) {
        uint2 e = ed[j];
        acc = fmaf(__uint_as_float(e.y), __ldg(x + (size_t)e.x * 16 + sub), acc);
    }
    out[(size_t)node * 16 + sub] = acc;
}

// ---------------------------------------------------------------------------
// CSR gather propagate, C == 32: warp per node, unroll-8 batched loads
// ---------------------------------------------------------------------------
__global__ void prop_csr_c32(const float* __restrict__ x, const uint2* __restrict__ ed,
                             const int* __restrict__ rs, float* __restrict__ out, int N) {
    int warp = (blockIdx.x * blockDim.x + threadIdx.x) >> 5;
    int lane = threadIdx.x & 31;
    if (warp >= N) return;
    int beg = rs[warp], end = rs[warp + 1];
    const float* xr = x + lane;
    float acc = 0.f;
    int j = beg;
    for (; j + 8 <= end; j += 8) {
        uint2 e[8];
#pragma unroll
        for (int k = 0; k < 8; k++) e[k] = ed[j + k];
        float v[8];
#pragma unroll
        for (int k = 0; k < 8; k++) v[k] = __ldg(xr + (size_t)e[k].x * 32);
#pragma unroll
        for (int k = 0; k < 8; k++) acc = fmaf(__uint_as_float(e[k].y), v[k], acc);
    }
    for (; j < end; j++) {
        uint2 e = ed[j];
        acc = fmaf(__uint_as_float(e.y), __ldg(xr + (size_t)e.x * 32), acc);
    }
    out[(size_t)warp * 32 + lane] = acc;
}

// ---------------------------------------------------------------------------
// CSR gather propagate, C == 4 (packed [z1|z2] per node): warp per node.
// lane = k*4 + c : 8 edge slots (k) x 4 channels (c). Reduce over k by shfl.
// ---------------------------------------------------------------------------
__global__ void prop_csr_c4(const float* __restrict__ x, const uint2* __restrict__ ed,
                            const int* __restrict__ rs, float* __restrict__ out, int N) {
    int warp = (blockIdx.x * blockDim.x + threadIdx.x) >> 5;
    int lane = threadIdx.x & 31;
    if (warp >= N) return;
    int k = lane >> 2;
    int c = lane & 3;
    int beg = rs[warp], end = rs[warp + 1];
    float acc = 0.f;
    for (int j = beg + k; j < end; j += 8) {
        uint2 e = ed[j];
        acc = fmaf(__uint_as_float(e.y), __ldg(x + (size_t)e.x * 4 + c), acc);
    }
#pragma unroll
    for (int off = 16; off >= 4; off >>= 1)
        acc += __shfl_down_sync(0xffffffffu, acc, off);
    if (lane < 4) out[(size_t)warp * 4 + c] = acc;
}

// ---------------------------------------------------------------------------
// Final layer tail: w = P(v) where v = t4[:, 2:4]; then
// y[n, c] = part[n, c] + t4[n, c] + 2 * w[c]         (c in {0,1})
// warp per node: lane = k*2 + c : 16 edge slots x 2 channels.
// ---------------------------------------------------------------------------
__global__ void prop2_final_k(const float* __restrict__ t4, const float* __restrict__ part,
                              const uint2* __restrict__ ed, const int* __restrict__ rs,
                              float* __restrict__ y, int N) {
    int warp = (blockIdx.x * blockDim.x + threadIdx.x) >> 5;
    int lane = threadIdx.x & 31;
    if (warp >= N) return;
    int k = lane >> 1;
    int c = lane & 1;
    int beg = rs[warp], end = rs[warp + 1];
    float acc = 0.f;
    for (int j = beg + k; j < end; j += 16) {
        uint2 e = ed[j];
        acc = fmaf(__uint_as_float(e.y), __ldg(t4 + (size_t)e.x * 4 + 2 + c), acc);
    }
#pragma unroll
    for (int off = 16; off >= 2; off >>= 1)
        acc += __shfl_down_sync(0xffffffffu, acc, off);
    if (lane < 2)
        y[(size_t)warp * 2 + c] = part[(size_t)warp * 2 + c]
                                + t4[(size_t)warp * 4 + c] + 2.f * acc;
}

// ---------------------------------------------------------------------------
// Layer-4 head GEMM: per node n,
//   part[n,co]  = h@W4[0][:,co] - h@W4[2][:,co]
//   zpack[n,0:2] = h@W4[1];  zpack[n,2:4] = h@W4[2]
// warp per node; W4 staged in smem transposed: sW[(k*2+co)*64 + ci].
// ---------------------------------------------------------------------------
__global__ void gemm_head_64_2(const float* __restrict__ h, const float* __restrict__ W,
                               float* __restrict__ part, float* __restrict__ zpack, int n) {
    __shared__ float sW[6 * 64];
    for (int i = threadIdx.x; i < 384; i += blockDim.x) {
        int k = i / 128, rem = i % 128, ci = rem / 2, co = rem % 2;
        sW[(k * 2 + co) * 64 + ci] = W[i];
    }
    __syncthreads();
    int warp = (blockIdx.x * blockDim.x + threadIdx.x) >> 5;
    int lane = threadIdx.x & 31;
    if (warp >= n) return;
    size_t base = (size_t)warp * 64;
    float a0 = h[base + lane];
    float a1 = h[base + lane + 32];
    float r[6];
#pragma unroll
    for (int m = 0; m < 6; m++) {
        const float* w = sW + m * 64;
        float acc = fmaf(a1, w[lane + 32], a0 * w[lane]);
#pragma unroll
        for (int off = 16; off > 0; off >>= 1)
            acc += __shfl_down_sync(0xffffffffu, acc, off);
        r[m] = acc;
    }
    if (lane == 0) {
        part[(size_t)warp * 2 + 0] = r[0] - r[4];
        part[(size_t)warp * 2 + 1] = r[1] - r[5];
        float4 z; z.x = r[2]; z.y = r[3]; z.z = r[4]; z.w = r[5];
        *reinterpret_cast<float4*>(zpack + (size_t)warp * 4) = z;
    }
}

// ---------------------------------------------------------------------------
// Combine 1->16
// ---------------------------------------------------------------------------
__global__ void combine_1_16(const float* __restrict__ f0, const float* __restrict__ t1,
                             const float* __restrict__ t2, const float* __restrict__ W,
                             float* __restrict__ out, int n) {
    __shared__ float sW[48];
    if (threadIdx.x < 48) sW[threadIdx.x] = W[threadIdx.x];
    __syncthreads();
    int tid = blockIdx.x * blockDim.x + threadIdx.x;
    int node = tid >> 4;
    int co = tid & 15;
    if (node >= n) return;
    float a = f0[node];
    float b = t1[node];
    float d = 2.f * t2[node] - a;
    float acc = a * sW[co] + b * sW[16 + co] + d * sW[32 + co];
    out[(size_t)node * 16 + co] = fmaxf(acc, 0.f);
}

// ---------------------------------------------------------------------------
// Combine 16->32: warp per node; shfl broadcast
// ---------------------------------------------------------------------------
__global__ void combine_16_32(const float* __restrict__ f0, const float* __restrict__ t1,
                              const float* __restrict__ t2, const float* __restrict__ W,
                              float* __restrict__ out, int n) {
    __shared__ float sW[3 * 16 * 32];
    for (int i = threadIdx.x; i < 3 * 16 * 32; i += blockDim.x) sW[i] = W[i];
    __syncthreads();
    int warp = (blockIdx.x * blockDim.x + threadIdx.x) >> 5;
    int lane = threadIdx.x & 31;
    if (warp >= n) return;
    int c = lane & 15;
    float a = f0[(size_t)warp * 16 + c];
    float b = t1[(size_t)warp * 16 + c];
    float d = 2.f * t2[(size_t)warp * 16 + c] - a;
    float acc = 0.f;
#pragma unroll
    for (int cc = 0; cc < 16; cc++) {
        float av = __shfl_sync(0xffffffffu, a, cc);
        float bv = __shfl_sync(0xffffffffu, b, cc);
        float dv = __shfl_sync(0xffffffffu, d, cc);
        acc = fmaf(av, sW[cc * 32 + lane], acc);
        acc = fmaf(bv, sW[512 + cc * 32 + lane], acc);
        acc = fmaf(dv, sW[1024 + cc * 32 + lane], acc);
    }
    out[(size_t)warp * 32 + lane] = fmaxf(acc, 0.f);
}

// ---------------------------------------------------------------------------
// Combine 32->64: warp per node; 2 couts per lane
// ---------------------------------------------------------------------------
__global__ void combine_32_64(const float* __restrict__ f0, const float* __restrict__ t1,
                              const float* __restrict__ t2, const float* __restrict__ W,
                              float* __restrict__ out, int n) {
    __shared__ float sW[3 * 32 * 64];
    for (int i = threadIdx.x; i < 3 * 32 * 64; i += blockDim.x) sW[i] = W[i];
    __syncthreads();
    int warp = (blockIdx.x * blockDim.x + threadIdx.x) >> 5;
    int lane = threadIdx.x & 31;
    if (warp >= n) return;
    float a = f0[(size_t)warp * 32 + lane];
    float b = t1[(size_t)warp * 32 + lane];
    float d = 2.f * t2[(size_t)warp * 32 + lane] - a;
    float acc0 = 0.f, acc1 = 0.f;
#pragma unroll
    for (int cc = 0; cc < 32; cc++) {
        float av = __shfl_sync(0xffffffffu, a, cc);
        float bv = __shfl_sync(0xffffffffu, b, cc);
        float dv = __shfl_sync(0xffffffffu, d, cc);
        const float* w0 = sW + cc * 64;
        const float* w1 = sW + 2048 + cc * 64;
        const float* w2 = sW + 4096 + cc * 64;
        acc0 = fmaf(av, w0[lane], acc0);
        acc0 = fmaf(bv, w1[lane], acc0);
        acc0 = fmaf(dv, w2[lane], acc0);
        acc1 = fmaf(av, w0[lane + 32], acc1);
        acc1 = fmaf(bv, w1[lane + 32], acc1);
        acc1 = fmaf(dv, w2[lane + 32], acc1);
    }
    out[(size_t)warp * 64 + lane] = fmaxf(acc0, 0.f);
    out[(size_t)warp * 64 + lane + 32] = fmaxf(acc1, 0.f);
}

extern "C" void kernel_launch(void* const* d_in, const int* in_sizes, int n_in,
                              void* d_out, int out_size) {
    const float* x = (const float*)d_in[0];
    const int* edge_index = (const int*)d_in[1];
    const float* ea = (const float*)d_in[2];
    const float* W1 = (const float*)d_in[3];
    const float* W2 = (const float*)d_in[4];
    const float* W3 = (const float*)d_in[5];
    const float* W4 = (const float*)d_in[6];

    const int N = in_sizes[0];
    const int E = in_sizes[2];
    const int* src = edge_index;
    const int* dst = edge_index + E;

    float *deg, *bufA, *bufB, *t1, *t2;
    int *cnt, *rs, *cur, *bsum;
    uint2* edges;
    cudaGetSymbolAddress((void**)&deg, g_deg);
    cudaGetSymbolAddress((void**)&cnt, g_cnt);
    cudaGetSymbolAddress((void**)&rs, g_rs);
    cudaGetSymbolAddress((void**)&cur, g_cur);
    cudaGetSymbolAddress((void**)&bsum, g_bsum);
    cudaGetSymbolAddress((void**)&edges, g_edges);
    cudaGetSymbolAddress((void**)&bufA, g_bufA);
    cudaGetSymbolAddress((void**)&bufB, g_bufB);
    cudaGetSymbolAddress((void**)&t1, g_t1);
    cudaGetSymbolAddress((void**)&t2, g_t2);

    // ---- build normalization + dst-sorted CSR ----
    zero_f_k<<<cdiv(N, 256), 256>>>(deg, N);
    zero_i_k<<<cdiv(N, 256), 256>>>(cnt, N);
    deg_hist_k<<<cdiv(E, 256), 256>>>(src, dst, ea, deg, cnt, E);
    int nb = cdiv(N, SCAN_ELEMS);
    bsum_k<<<nb, SCAN_TPB>>>(cnt, bsum, N);
    bscan_k<<<1, 128>>>(bsum, nb, rs + N);  // rs[N] = E
    expand_k<<<nb, SCAN_TPB>>>(cnt, bsum, rs, cur, N);
    scatter_k<<<cdiv(E, 256), 256>>>(src, dst, ea, deg, cur, edges, E);

    const int WPB = 256;
    int grid_n = cdiv((long long)N * 32, WPB);
    int grid_n2 = cdiv((long long)cdiv(N, 2) * 32, WPB);

    // ---- layer 1: 1 -> 16, relu ----
    prop_csr_c1<<<grid_n, WPB>>>(x, edges, rs, t1, N);
    prop_csr_c1<<<grid_n, WPB>>>(t1, edges, rs, t2, N);
    combine_1_16<<<cdiv((long long)N * 16, 256), 256>>>(x, t1, t2, W1, bufA, N);

    // ---- layer 2: 16 -> 32, relu ----
    prop_csr_c16<<<grid_n2, WPB>>>(bufA, edges, rs, t1, N);
    prop_csr_c16<<<grid_n2, WPB>>>(t1, edges, rs, t2, N);
    combine_16_32<<<grid_n, WPB>>>(bufA, t1, t2, W2, bufB, N);

    // ---- layer 3: 32 -> 64, relu ----
    prop_csr_c32<<<grid_n, WPB>>>(bufB, edges, rs, t1, N);
    prop_csr_c32<<<grid_n, WPB>>>(t1, edges, rs, t2, N);
    combine_32_64<<<grid_n, WPB>>>(bufB, t1, t2, W3, bufA, N);

    // ---- layer 4: 64 -> 2 via project-then-propagate ----
    // part = h@W0 - h@W2 ; zpack = [h@W1 | h@W2]
    gemm_head_64_2<<<grid_n, WPB>>>(bufA, W4, bufB, t1, N);
    // t2[:,0:4] = P zpack  ( [P z1 | P z2] )
    prop_csr_c4<<<grid_n, WPB>>>(t1, edges, rs, t2, N);
    // y = part + (P z1) + 2 P(P z2)
    prop2_final_k<<<grid_n, WPB>>>(t2, bufB, edges, rs, (float*)d_out, N);
}

// round 5
// speedup vs baseline: 2.0746x; 1.0483x over previous
#include <cuda_runtime.h>
#include <cuda_bf16.h>
#include <cstdint>

#define NMAX 100000
#define EMAX 3200000

// Scratch (device globals: allocation is forbidden).
__device__ float g_deg[NMAX];
__device__ int   g_cnt[NMAX];
__device__ int   g_rs[NMAX + 1];
__device__ int   g_cur[NMAX];
__device__ int   g_bsum[128];
__device__ uint2 g_edges[EMAX];
__device__ float g_bufA[NMAX * 64];
__device__ float g_bufB[NMAX * 64];
__device__ float g_t1[NMAX * 64];
__device__ float g_t2[NMAX * 64];
__device__ __nv_bfloat16 g_xb[NMAX * 32];   // bf16 shadow of prop input
__device__ __nv_bfloat16 g_tb[NMAX * 32];   // bf16 shadow of t1

static inline int cdiv(long long a, int b) { return (int)((a + b - 1) / b); }

// ---------------------------------------------------------------------------
// fused zero of deg (float) and cnt (int)
// ---------------------------------------------------------------------------
__global__ void zero_build_k(float* deg, int* cnt, int n) {
    int i = blockIdx.x * blockDim.x + threadIdx.x;
    if (i < n) { deg[i] = 0.f; cnt[i] = 0; }
}

// ---------------------------------------------------------------------------
// deg[src[e]] += ea[e];  cnt[dst[e]] += 1
// ---------------------------------------------------------------------------
__global__ void deg_hist_k(const int* __restrict__ src, const int* __restrict__ dst,
                           const float* __restrict__ ea,
                           float* __restrict__ deg, int* __restrict__ cnt, int E) {
    int e = blockIdx.x * blockDim.x + threadIdx.x;
    if (e >= E) return;
    atomicAdd(&deg[src[e]], ea[e]);
    atomicAdd(&cnt[dst[e]], 1);
}

// ---------------------------------------------------------------------------
// Parallel exclusive scan of cnt -> rs, cur.
// ---------------------------------------------------------------------------
#define SCAN_TPB 256
#define SCAN_ELEMS 1024

__global__ void bsum_k(const int* __restrict__ cnt, int* __restrict__ bsum, int n) {
    int base = blockIdx.x * SCAN_ELEMS;
    int s = 0;
    for (int i = threadIdx.x; i < SCAN_ELEMS; i += SCAN_TPB) {
        int idx = base + i;
        s += (idx < n) ? cnt[idx] : 0;
    }
#pragma unroll
    for (int o = 16; o > 0; o >>= 1) s += __shfl_down_sync(0xffffffffu, s, o);
    __shared__ int ws[SCAN_TPB / 32];
    if ((threadIdx.x & 31) == 0) ws[threadIdx.x >> 5] = s;
    __syncthreads();
    if (threadIdx.x == 0) {
        int t = 0;
#pragma unroll
        for (int w = 0; w < SCAN_TPB / 32; w++) t += ws[w];
        bsum[blockIdx.x] = t;
    }
}

__global__ void bscan_k(int* __restrict__ bsum, int nb, int* __restrict__ total) {
    __shared__ int sm[128];
    int v = (threadIdx.x < nb) ? bsum[threadIdx.x] : 0;
    sm[threadIdx.x] = v;
    __syncthreads();
    for (int o = 1; o < 128; o <<= 1) {
        int t = sm[threadIdx.x];
        int add = (threadIdx.x >= (unsigned)o) ? sm[threadIdx.x - o] : 0;
        __syncthreads();
        sm[threadIdx.x] = t + add;
        __syncthreads();
    }
    if (threadIdx.x < nb) bsum[threadIdx.x] = sm[threadIdx.x] - v;
    if (threadIdx.x == 127) *total = sm[127];
}

__global__ void expand_k(const int* __restrict__ cnt, const int* __restrict__ bsum,
                         int* __restrict__ rs, int* __restrict__ cur, int n) {
    int base = blockIdx.x * SCAN_ELEMS + threadIdx.x * 4;
    int c0 = 0, c1 = 0, c2 = 0, c3 = 0;
    if (base + 3 < n) {
        int4 v = *reinterpret_cast<const int4*>(cnt + base);
        c0 = v.x; c1 = v.y; c2 = v.z; c3 = v.w;
    } else {
        if (base + 0 < n) c0 = cnt[base + 0];
        if (base + 1 < n) c1 = cnt[base + 1];
        if (base + 2 < n) c2 = cnt[base + 2];
        if (base + 3 < n) c3 = cnt[base + 3];
    }
    int ts = c0 + c1 + c2 + c3;
    int lane = threadIdx.x & 31, wid = threadIdx.x >> 5;
    int inc = ts;
#pragma unroll
    for (int o = 1; o < 32; o <<= 1) {
        int v = __shfl_up_sync(0xffffffffu, inc, o);
        if (lane >= o) inc += v;
    }
    __shared__ int wsum[SCAN_TPB / 32];
    __shared__ int woff[SCAN_TPB / 32];
    if (lane == 31) wsum[wid] = inc;
    __syncthreads();
    if (threadIdx.x == 0) {
        int r = 0;
#pragma unroll
        for (int w = 0; w < SCAN_TPB / 32; w++) { woff[w] = r; r += wsum[w]; }
    }
    __syncthreads();
    int r = (inc - ts) + woff[wid] + bsum[blockIdx.x];
    if (base + 0 < n) { rs[base + 0] = r; cur[base + 0] = r; r += c0; }
    if (base + 1 < n) { rs[base + 1] = r; cur[base + 1] = r; r += c1; }
    if (base + 2 < n) { rs[base + 2] = r; cur[base + 2] = r; r += c2; }
    if (base + 3 < n) { rs[base + 3] = r; cur[base + 3] = r; r += c3; }
}

// ---------------------------------------------------------------------------
// scatter: compute norm inline, place packed {src, norm} at cursor slot
// ---------------------------------------------------------------------------
__global__ void scatter_k(const int* __restrict__ src, const int* __restrict__ dst,
                          const float* __restrict__ ea, const float* __restrict__ deg,
                          int* __restrict__ cur, uint2* __restrict__ ed, int E) {
    int e = blockIdx.x * blockDim.x + threadIdx.x;
    if (e >= E) return;
    int s = src[e];
    int d = dst[e];
    float ds = deg[s];
    float dd = deg[d];
    float is = ds > 0.f ? rsqrtf(ds) : 0.f;
    float id = dd > 0.f ? rsqrtf(dd) : 0.f;
    float w = -is * ea[e] * id;
    int slot = atomicAdd(&cur[d], 1);
    ed[slot] = make_uint2((unsigned)s, __float_as_uint(w));
}

// ---------------------------------------------------------------------------
// CSR gather propagate, C == 1: warp per node, lanes over edges
// ---------------------------------------------------------------------------
__global__ void prop_csr_c1(const float* __restrict__ x, const uint2* __restrict__ ed,
                            const int* __restrict__ rs, float* __restrict__ out, int N) {
    int warp = (blockIdx.x * blockDim.x + threadIdx.x) >> 5;
    int lane = threadIdx.x & 31;
    if (warp >= N) return;
    int beg = rs[warp], end = rs[warp + 1];
    float acc = 0.f;
    for (int j = beg + lane; j < end; j += 32) {
        uint2 e = ed[j];
        acc += __uint_as_float(e.y) * __ldg(x + e.x);
    }
#pragma unroll
    for (int off = 16; off > 0; off >>= 1)
        acc += __shfl_down_sync(0xffffffffu, acc, off);
    if (lane == 0) out[warp] = acc;
}

// ---------------------------------------------------------------------------
// bf16 CSR gather, C == 16: warp per node, 4 edges / instruction.
// grp = lane>>3 (edge slot), sub = lane&7 (bf162 channel pair).
// ---------------------------------------------------------------------------
template <bool WRITE_B>
__global__ void prop_c16_bf16(const __nv_bfloat16* __restrict__ xb,
                              const uint2* __restrict__ ed, const int* __restrict__ rs,
                              float* __restrict__ out, __nv_bfloat16* __restrict__ outb,
                              int N) {
    int warp = (blockIdx.x * blockDim.x + threadIdx.x) >> 5;
    int lane = threadIdx.x & 31;
    if (warp >= N) return;
    int grp = lane >> 3;
    int sub = lane & 7;
    int beg = rs[warp], end = rs[warp + 1];
    float ax = 0.f, ay = 0.f;
    int j = beg;
    for (; j + 8 <= end; j += 8) {
        uint2 e0 = ed[j + grp];
        uint2 e1 = ed[j + 4 + grp];
        __nv_bfloat162 v0 = *reinterpret_cast<const __nv_bfloat162*>(
            xb + (size_t)e0.x * 16 + sub * 2);
        __nv_bfloat162 v1 = *reinterpret_cast<const __nv_bfloat162*>(
            xb + (size_t)e1.x * 16 + sub * 2);
        float2 f0 = __bfloat1622float2(v0);
        float2 f1 = __bfloat1622float2(v1);
        float w0 = __uint_as_float(e0.y);
        float w1 = __uint_as_float(e1.y);
        ax = fmaf(w0, f0.x, ax); ay = fmaf(w0, f0.y, ay);
        ax = fmaf(w1, f1.x, ax); ay = fmaf(w1, f1.y, ay);
    }
    for (; j < end; j += 4) {
        int idx = j + grp;
        if (idx < end) {
            uint2 e = ed[idx];
            __nv_bfloat162 v = *reinterpret_cast<const __nv_bfloat162*>(
                xb + (size_t)e.x * 16 + sub * 2);
            float2 f = __bfloat1622float2(v);
            float w = __uint_as_float(e.y);
            ax = fmaf(w, f.x, ax); ay = fmaf(w, f.y, ay);
        }
    }
    ax += __shfl_xor_sync(0xffffffffu, ax, 8);
    ay += __shfl_xor_sync(0xffffffffu, ay, 8);
    ax += __shfl_xor_sync(0xffffffffu, ax, 16);
    ay += __shfl_xor_sync(0xffffffffu, ay, 16);
    if (lane < 8) {
        float2 r; r.x = ax; r.y = ay;
        *reinterpret_cast<float2*>(out + (size_t)warp * 16 + sub * 2) = r;
        if (WRITE_B) {
            __nv_bfloat162 b = __float22bfloat162_rn(r);
            *reinterpret_cast<__nv_bfloat162*>(outb + (size_t)warp * 16 + sub * 2) = b;
        }
    }
}

// ---------------------------------------------------------------------------
// bf16 CSR gather, C == 32: warp per node, 2 edges / instruction, unroll 4.
// grp = lane>>4 (edge slot), sub = lane&15 (bf162 channel pair).
// ---------------------------------------------------------------------------
template <bool WRITE_B>
__global__ void prop_c32_bf16(const __nv_bfloat16* __restrict__ xb,
                              const uint2* __restrict__ ed, const int* __restrict__ rs,
                              float* __restrict__ out, __nv_bfloat16* __restrict__ outb,
                              int N) {
    int warp = (blockIdx.x * blockDim.x + threadIdx.x) >> 5;
    int lane = threadIdx.x & 31;
    if (warp >= N) return;
    int grp = lane >> 4;
    int sub = lane & 15;
    int beg = rs[warp], end = rs[warp + 1];
    float ax = 0.f, ay = 0.f;
    int j = beg;
    for (; j + 8 <= end; j += 8) {
        uint2 e[4];
#pragma unroll
        for (int k = 0; k < 4; k++) e[k] = ed[j + k * 2 + grp];
        float2 f[4];
#pragma unroll
        for (int k = 0; k < 4; k++) {
            __nv_bfloat162 v = *reinterpret_cast<const __nv_bfloat162*>(
                xb + (size_t)e[k].x * 32 + sub * 2);
            f[k] = __bfloat1622float2(v);
        }
#pragma unroll
        for (int k = 0; k < 4; k++) {
            float w = __uint_as_float(e[k].y);
            ax = fmaf(w, f[k].x, ax);
            ay = fmaf(w, f[k].y, ay);
        }
    }
    for (; j < end; j += 2) {
        int idx = j + grp;
        if (idx < end) {
            uint2 e = ed[idx];
            __nv_bfloat162 v = *reinterpret_cast<const __nv_bfloat162*>(
                xb + (size_t)e.x * 32 + sub * 2);
            float2 f = __bfloat1622float2(v);
            float w = __uint_as_float(e.y);
            ax = fmaf(w, f.x, ax); ay = fmaf(w, f.y, ay);
        }
    }
    ax += __shfl_xor_sync(0xffffffffu, ax, 16);
    ay += __shfl_xor_sync(0xffffffffu, ay, 16);
    if (lane < 16) {
        float2 r; r.x = ax; r.y = ay;
        *reinterpret_cast<float2*>(out + (size_t)warp * 32 + sub * 2) = r;
        if (WRITE_B) {
            __nv_bfloat162 b = __float22bfloat162_rn(r);
            *reinterpret_cast<__nv_bfloat162*>(outb + (size_t)warp * 32 + sub * 2) = b;
        }
    }
}

// ---------------------------------------------------------------------------
// CSR gather propagate, C == 4 (packed [z1|z2] per node)
// ---------------------------------------------------------------------------
__global__ void prop_csr_c4(const float* __restrict__ x, const uint2* __restrict__ ed,
                            const int* __restrict__ rs, float* __restrict__ out, int N) {
    int warp = (blockIdx.x * blockDim.x + threadIdx.x) >> 5;
    int lane = threadIdx.x & 31;
    if (warp >= N) return;
    int k = lane >> 2;
    int c = lane & 3;
    int beg = rs[warp], end = rs[warp + 1];
    float acc = 0.f;
    for (int j = beg + k; j < end; j += 8) {
        uint2 e = ed[j];
        acc = fmaf(__uint_as_float(e.y), __ldg(x + (size_t)e.x * 4 + c), acc);
    }
#pragma unroll
    for (int off = 16; off >= 4; off >>= 1)
        acc += __shfl_down_sync(0xffffffffu, acc, off);
    if (lane < 4) out[(size_t)warp * 4 + c] = acc;
}

// ---------------------------------------------------------------------------
// Final layer tail (see round 4)
// ---------------------------------------------------------------------------
__global__ void prop2_final_k(const float* __restrict__ t4, const float* __restrict__ part,
                              const uint2* __restrict__ ed, const int* __restrict__ rs,
                              float* __restrict__ y, int N) {
    int warp = (blockIdx.x * blockDim.x + threadIdx.x) >> 5;
    int lane = threadIdx.x & 31;
    if (warp >= N) return;
    int k = lane >> 1;
    int c = lane & 1;
    int beg = rs[warp], end = rs[warp + 1];
    float acc = 0.f;
    for (int j = beg + k; j < end; j += 16) {
        uint2 e = ed[j];
        acc = fmaf(__uint_as_float(e.y), __ldg(t4 + (size_t)e.x * 4 + 2 + c), acc);
    }
#pragma unroll
    for (int off = 16; off >= 2; off >>= 1)
        acc += __shfl_down_sync(0xffffffffu, acc, off);
    if (lane < 2)
        y[(size_t)warp * 2 + c] = part[(size_t)warp * 2 + c]
                                + t4[(size_t)warp * 4 + c] + 2.f * acc;
}

// ---------------------------------------------------------------------------
// Layer-4 head GEMM (see round 4)
// ---------------------------------------------------------------------------
__global__ void gemm_head_64_2(const float* __restrict__ h, const float* __restrict__ W,
                               float* __restrict__ part, float* __restrict__ zpack, int n) {
    __shared__ float sW[6 * 64];
    for (int i = threadIdx.x; i < 384; i += blockDim.x) {
        int k = i / 128, rem = i % 128, ci = rem / 2, co = rem % 2;
        sW[(k * 2 + co) * 64 + ci] = W[i];
    }
    __syncthreads();
    int warp = (blockIdx.x * blockDim.x + threadIdx.x) >> 5;
    int lane = threadIdx.x & 31;
    if (warp >= n) return;
    size_t base = (size_t)warp * 64;
    float a0 = h[base + lane];
    float a1 = h[base + lane + 32];
    float r[6];
#pragma unroll
    for (int m = 0; m < 6; m++) {
        const float* w = sW + m * 64;
        float acc = fmaf(a1, w[lane + 32], a0 * w[lane]);
#pragma unroll
        for (int off = 16; off > 0; off >>= 1)
            acc += __shfl_down_sync(0xffffffffu, acc, off);
        r[m] = acc;
    }
    if (lane == 0) {
        part[(size_t)warp * 2 + 0] = r[0] - r[4];
        part[(size_t)warp * 2 + 1] = r[1] - r[5];
        float4 z; z.x = r[2]; z.y = r[3]; z.z = r[4]; z.w = r[5];
        *reinterpret_cast<float4*>(zpack + (size_t)warp * 4) = z;
    }
}

// ---------------------------------------------------------------------------
// Combine 1->16: also emits bf16 copy for prop_c16
// ---------------------------------------------------------------------------
__global__ void combine_1_16(const float* __restrict__ f0, const float* __restrict__ t1,
                             const float* __restrict__ t2, const float* __restrict__ W,
                             float* __restrict__ out, __nv_bfloat16* __restrict__ outb,
                             int n) {
    __shared__ float sW[48];
    if (threadIdx.x < 48) sW[threadIdx.x] = W[threadIdx.x];
    __syncthreads();
    int tid = blockIdx.x * blockDim.x + threadIdx.x;
    int node = tid >> 4;
    int co = tid & 15;
    if (node >= n) return;
    float a = f0[node];
    float b = t1[node];
    float d = 2.f * t2[node] - a;
    float acc = a * sW[co] + b * sW[16 + co] + d * sW[32 + co];
    float r = fmaxf(acc, 0.f);
    out[(size_t)node * 16 + co] = r;
    outb[(size_t)node * 16 + co] = __float2bfloat16_rn(r);
}

// ---------------------------------------------------------------------------
// Combine 16->32: warp per node; emits bf16 copy for prop_c32
// ---------------------------------------------------------------------------
__global__ void combine_16_32(const float* __restrict__ f0, const float* __restrict__ t1,
                              const float* __restrict__ t2, const float* __restrict__ W,
                              float* __restrict__ out, __nv_bfloat16* __restrict__ outb,
                              int n) {
    __shared__ float sW[3 * 16 * 32];
    for (int i = threadIdx.x; i < 3 * 16 * 32; i += blockDim.x) sW[i] = W[i];
    __syncthreads();
    int warp = (blockIdx.x * blockDim.x + threadIdx.x) >> 5;
    int lane = threadIdx.x & 31;
    if (warp >= n) return;
    int c = lane & 15;
    float a = f0[(size_t)warp * 16 + c];
    float b = t1[(size_t)warp * 16 + c];
    float d = 2.f * t2[(size_t)warp * 16 + c] - a;
    float acc = 0.f;
#pragma unroll
    for (int cc = 0; cc < 16; cc++) {
        float av = __shfl_sync(0xffffffffu, a, cc);
        float bv = __shfl_sync(0xffffffffu, b, cc);
        float dv = __shfl_sync(0xffffffffu, d, cc);
        acc = fmaf(av, sW[cc * 32 + lane], acc);
        acc = fmaf(bv, sW[512 + cc * 32 + lane], acc);
        acc = fmaf(dv, sW[1024 + cc * 32 + lane], acc);
    }
    float r = fmaxf(acc, 0.f);
    out[(size_t)warp * 32 + lane] = r;
    outb[(size_t)warp * 32 + lane] = __float2bfloat16_rn(r);
}

// ---------------------------------------------------------------------------
// Combine 32->64: warp per node (fp32 only; layer 4 consumes fp32)
// ---------------------------------------------------------------------------
__global__ void combine_32_64(const float* __restrict__ f0, const float* __restrict__ t1,
                              const float* __restrict__ t2, const float* __restrict__ W,
                              float* __restrict__ out, int n) {
    __shared__ float sW[3 * 32 * 64];
    for (int i = threadIdx.x; i < 3 * 32 * 64; i += blockDim.x) sW[i] = W[i];
    __syncthreads();
    int warp = (blockIdx.x * blockDim.x + threadIdx.x) >> 5;
    int lane = threadIdx.x & 31;
    if (warp >= n) return;
    float a = f0[(size_t)warp * 32 + lane];
    float b = t1[(size_t)warp * 32 + lane];
    float d = 2.f * t2[(size_t)warp * 32 + lane] - a;
    float acc0 = 0.f, acc1 = 0.f;
#pragma unroll
    for (int cc = 0; cc < 32; cc++) {
        float av = __shfl_sync(0xffffffffu, a, cc);
        float bv = __shfl_sync(0xffffffffu, b, cc);
        float dv = __shfl_sync(0xffffffffu, d, cc);
        const float* w0 = sW + cc * 64;
        const float* w1 = sW + 2048 + cc * 64;
        const float* w2 = sW + 4096 + cc * 64;
        acc0 = fmaf(av, w0[lane], acc0);
        acc0 = fmaf(bv, w1[lane], acc0);
        acc0 = fmaf(dv, w2[lane], acc0);
        acc1 = fmaf(av, w0[lane + 32], acc1);
        acc1 = fmaf(bv, w1[lane + 32], acc1);
        acc1 = fmaf(dv, w2[lane + 32], acc1);
    }
    out[(size_t)warp * 64 + lane] = fmaxf(acc0, 0.f);
    out[(size_t)warp * 64 + lane + 32] = fmaxf(acc1, 0.f);
}

extern "C" void kernel_launch(void* const* d_in, const int* in_sizes, int n_in,
                              void* d_out, int out_size) {
    const float* x = (const float*)d_in[0];
    const int* edge_index = (const int*)d_in[1];
    const float* ea = (const float*)d_in[2];
    const float* W1 = (const float*)d_in[3];
    const float* W2 = (const float*)d_in[4];
    const float* W3 = (const float*)d_in[5];
    const float* W4 = (const float*)d_in[6];

    const int N = in_sizes[0];
    const int E = in_sizes[2];
    const int* src = edge_index;
    const int* dst = edge_index + E;

    float *deg, *bufA, *bufB, *t1, *t2;
    int *cnt, *rs, *cur, *bsum;
    uint2* edges;
    __nv_bfloat16 *xb, *tb;
    cudaGetSymbolAddress((void**)&deg, g_deg);
    cudaGetSymbolAddress((void**)&cnt, g_cnt);
    cudaGetSymbolAddress((void**)&rs, g_rs);
    cudaGetSymbolAddress((void**)&cur, g_cur);
    cudaGetSymbolAddress((void**)&bsum, g_bsum);
    cudaGetSymbolAddress((void**)&edges, g_edges);
    cudaGetSymbolAddress((void**)&bufA, g_bufA);
    cudaGetSymbolAddress((void**)&bufB, g_bufB);
    cudaGetSymbolAddress((void**)&t1, g_t1);
    cudaGetSymbolAddress((void**)&t2, g_t2);
    cudaGetSymbolAddress((void**)&xb, g_xb);
    cudaGetSymbolAddress((void**)&tb, g_tb);

    // ---- build normalization + dst-sorted CSR ----
    zero_build_k<<<cdiv(N, 256), 256>>>(deg, cnt, N);
    deg_hist_k<<<cdiv(E, 256), 256>>>(src, dst, ea, deg, cnt, E);
    int nb = cdiv(N, SCAN_ELEMS);
    bsum_k<<<nb, SCAN_TPB>>>(cnt, bsum, N);
    bscan_k<<<1, 128>>>(bsum, nb, rs + N);
    expand_k<<<nb, SCAN_TPB>>>(cnt, bsum, rs, cur, N);
    scatter_k<<<cdiv(E, 256), 256>>>(src, dst, ea, deg, cur, edges, E);

    const int WPB = 256;
    int grid_n = cdiv((long long)N * 32, WPB);

    // ---- layer 1: 1 -> 16, relu ----
    prop_csr_c1<<<grid_n, WPB>>>(x, edges, rs, t1, N);
    prop_csr_c1<<<grid_n, WPB>>>(t1, edges, rs, t2, N);
    combine_1_16<<<cdiv((long long)N * 16, 256), 256>>>(x, t1, t2, W1, bufA, xb, N);

    // ---- layer 2: 16 -> 32, relu (bf16 gathers) ----
    prop_c16_bf16<true><<<grid_n, WPB>>>(xb, edges, rs, t1, tb, N);
    prop_c16_bf16<false><<<grid_n, WPB>>>(tb, edges, rs, t2, nullptr, N);
    combine_16_32<<<grid_n, WPB>>>(bufA, t1, t2, W2, bufB, xb, N);

    // ---- layer 3: 32 -> 64, relu (bf16 gathers) ----
    prop_c32_bf16<true><<<grid_n, WPB>>>(xb, edges, rs, t1, tb, N);
    prop_c32_bf16<false><<<grid_n, WPB>>>(tb, edges, rs, t2, nullptr, N);
    combine_32_64<<<grid_n, WPB>>>(bufB, t1, t2, W3, bufA, N);

    // ---- layer 4: 64 -> 2 via project-then-propagate ----
    gemm_head_64_2<<<grid_n, WPB>>>(bufA, W4, bufB, t1, N);
    prop_csr_c4<<<grid_n, WPB>>>(t1, edges, rs, t2, N);
    prop2_final_k<<<grid_n, WPB>>>(t2, bufB, edges, rs, (float*)d_out, N);
}

// round 6
// speedup vs baseline: 2.1164x; 1.0201x over previous
#include <cuda_runtime.h>
#include <cuda_bf16.h>
#include <cstdint>

#define NMAX 100000
#define EMAX 3200000

// Scratch (device globals: allocation is forbidden).
__device__ float g_deg[NMAX];
__device__ float g_dis[NMAX];
__device__ float g_xs[NMAX];            // dis * x (layer-1 scaled input)
__device__ int   g_cnt[NMAX];
__device__ int   g_rs[NMAX + 1];
__device__ int   g_cur[NMAX];
__device__ int   g_bsum[128];
__device__ uint2 g_edges[EMAX];         // packed {src, ea}
__device__ float g_bufA[NMAX * 64];
__device__ float g_bufB[NMAX * 64];
__device__ float g_t1[NMAX * 64];
__device__ float g_t1s[NMAX];           // dis * t1 (layer-1 chain)
__device__ float g_t2[NMAX * 64];
__device__ __nv_bfloat16 g_xb[NMAX * 32];   // bf16 shadow (dis-scaled)
__device__ __nv_bfloat16 g_tb[NMAX * 32];   // bf16 shadow of t1 (dis-scaled)

static inline int cdiv(long long a, int b) { return (int)((a + b - 1) / b); }

// ---------------------------------------------------------------------------
// fused zero of deg (float) and cnt (int)
// ---------------------------------------------------------------------------
__global__ void zero_build_k(float* deg, int* cnt, int n) {
    int i = blockIdx.x * blockDim.x + threadIdx.x;
    if (i < n) { deg[i] = 0.f; cnt[i] = 0; }
}

// ---------------------------------------------------------------------------
// deg[src[e]] += ea[e];  cnt[dst[e]] += 1
// ---------------------------------------------------------------------------
__global__ void deg_hist_k(const int* __restrict__ src, const int* __restrict__ dst,
                           const float* __restrict__ ea,
                           float* __restrict__ deg, int* __restrict__ cnt, int E) {
    int e = blockIdx.x * blockDim.x + threadIdx.x;
    if (e >= E) return;
    atomicAdd(&deg[src[e]], ea[e]);
    atomicAdd(&cnt[dst[e]], 1);
}

// ---------------------------------------------------------------------------
// dis[i] = deg>0 ? rsqrt(deg) : 0 ; xs[i] = dis[i]*x[i]
// ---------------------------------------------------------------------------
__global__ void dis_k(const float* __restrict__ deg, const float* __restrict__ x,
                      float* __restrict__ dis, float* __restrict__ xs, int n) {
    int i = blockIdx.x * blockDim.x + threadIdx.x;
    if (i >= n) return;
    float d = deg[i];
    float r = d > 0.f ? rsqrtf(d) : 0.f;
    dis[i] = r;
    xs[i] = r * x[i];
}

// ---------------------------------------------------------------------------
// Parallel exclusive scan of cnt -> rs, cur.
// ---------------------------------------------------------------------------
#define SCAN_TPB 256
#define SCAN_ELEMS 1024

__global__ void bsum_k(const int* __restrict__ cnt, int* __restrict__ bsum, int n) {
    int base = blockIdx.x * SCAN_ELEMS;
    int s = 0;
    for (int i = threadIdx.x; i < SCAN_ELEMS; i += SCAN_TPB) {
        int idx = base + i;
        s += (idx < n) ? cnt[idx] : 0;
    }
#pragma unroll
    for (int o = 16; o > 0; o >>= 1) s += __shfl_down_sync(0xffffffffu, s, o);
    __shared__ int ws[SCAN_TPB / 32];
    if ((threadIdx.x & 31) == 0) ws[threadIdx.x >> 5] = s;
    __syncthreads();
    if (threadIdx.x == 0) {
        int t = 0;
#pragma unroll
        for (int w = 0; w < SCAN_TPB / 32; w++) t += ws[w];
        bsum[blockIdx.x] = t;
    }
}

__global__ void bscan_k(int* __restrict__ bsum, int nb, int* __restrict__ total) {
    __shared__ int sm[128];
    int v = (threadIdx.x < nb) ? bsum[threadIdx.x] : 0;
    sm[threadIdx.x] = v;
    __syncthreads();
    for (int o = 1; o < 128; o <<= 1) {
        int t = sm[threadIdx.x];
        int add = (threadIdx.x >= (unsigned)o) ? sm[threadIdx.x - o] : 0;
        __syncthreads();
        sm[threadIdx.x] = t + add;
        __syncthreads();
    }
    if (threadIdx.x < nb) bsum[threadIdx.x] = sm[threadIdx.x] - v;
    if (threadIdx.x == 127) *total = sm[127];
}

__global__ void expand_k(const int* __restrict__ cnt, const int* __restrict__ bsum,
                         int* __restrict__ rs, int* __restrict__ cur, int n) {
    int base = blockIdx.x * SCAN_ELEMS + threadIdx.x * 4;
    int c0 = 0, c1 = 0, c2 = 0, c3 = 0;
    if (base + 3 < n) {
        int4 v = *reinterpret_cast<const int4*>(cnt + base);
        c0 = v.x; c1 = v.y; c2 = v.z; c3 = v.w;
    } else {
        if (base + 0 < n) c0 = cnt[base + 0];
        if (base + 1 < n) c1 = cnt[base + 1];
        if (base + 2 < n) c2 = cnt[base + 2];
        if (base + 3 < n) c3 = cnt[base + 3];
    }
    int ts = c0 + c1 + c2 + c3;
    int lane = threadIdx.x & 31, wid = threadIdx.x >> 5;
    int inc = ts;
#pragma unroll
    for (int o = 1; o < 32; o <<= 1) {
        int v = __shfl_up_sync(0xffffffffu, inc, o);
        if (lane >= o) inc += v;
    }
    __shared__ int wsum[SCAN_TPB / 32];
    __shared__ int woff[SCAN_TPB / 32];
    if (lane == 31) wsum[wid] = inc;
    __syncthreads();
    if (threadIdx.x == 0) {
        int r = 0;
#pragma unroll
        for (int w = 0; w < SCAN_TPB / 32; w++) { woff[w] = r; r += wsum[w]; }
    }
    __syncthreads();
    int r = (inc - ts) + woff[wid] + bsum[blockIdx.x];
    if (base + 0 < n) { rs[base + 0] = r; cur[base + 0] = r; r += c0; }
    if (base + 1 < n) { rs[base + 1] = r; cur[base + 1] = r; r += c1; }
    if (base + 2 < n) { rs[base + 2] = r; cur[base + 2] = r; r += c2; }
    if (base + 3 < n) { rs[base + 3] = r; cur[base + 3] = r; r += c3; }
}

// ---------------------------------------------------------------------------
// scatter: records are just {src, ea} — no deg dependency.
// ---------------------------------------------------------------------------
__global__ void scatter_k(const int* __restrict__ src, const int* __restrict__ dst,
                          const float* __restrict__ ea,
                          int* __restrict__ cur, uint2* __restrict__ ed, int E) {
    int e = blockIdx.x * blockDim.x + threadIdx.x;
    if (e >= E) return;
    int d = dst[e];
    int slot = atomicAdd(&cur[d], 1);
    ed[slot] = make_uint2((unsigned)src[e], __float_as_uint(ea[e]));
}

// ---------------------------------------------------------------------------
// C == 1 props. First pass: out = -dis[d]*acc, outs = dis[d]*out.
// Second pass: out = -dis[d]*acc only.
// ---------------------------------------------------------------------------
template <bool WRITE_S>
__global__ void prop_c1(const float* __restrict__ xs, const float* __restrict__ dis,
                        const uint2* __restrict__ ed, const int* __restrict__ rs,
                        float* __restrict__ out, float* __restrict__ outs, int N) {
    int warp = (blockIdx.x * blockDim.x + threadIdx.x) >> 5;
    int lane = threadIdx.x & 31;
    if (warp >= N) return;
    int beg = rs[warp], end = rs[warp + 1];
    float acc = 0.f;
    for (int j = beg + lane; j < end; j += 32) {
        uint2 e = ed[j];
        acc += __uint_as_float(e.y) * __ldg(xs + e.x);
    }
#pragma unroll
    for (int off = 16; off > 0; off >>= 1)
        acc += __shfl_down_sync(0xffffffffu, acc, off);
    if (lane == 0) {
        float di = dis[warp];
        float r = -di * acc;
        out[warp] = r;
        if (WRITE_S) outs[warp] = di * r;
    }
}

// ---------------------------------------------------------------------------
// bf16 CSR gather, C == 16: warp per node, 16 edges / iteration.
// grp = lane>>3 (4 edge slots), sub = lane&7 (bf162 channel pair).
// Input shadow xb already carries dis[s]; epilogue applies -dis[d].
// ---------------------------------------------------------------------------
template <bool WRITE_B>
__global__ void prop_c16_bf16(const __nv_bfloat16* __restrict__ xb,
                              const float* __restrict__ dis,
                              const uint2* __restrict__ ed, const int* __restrict__ rs,
                              float* __restrict__ out, __nv_bfloat16* __restrict__ outb,
                              int N) {
    int warp = (blockIdx.x * blockDim.x + threadIdx.x) >> 5;
    int lane = threadIdx.x & 31;
    if (warp >= N) return;
    int grp = lane >> 3;
    int sub = lane & 7;
    int beg = rs[warp], end = rs[warp + 1];
    float ax = 0.f, ay = 0.f;
    int j = beg;
    for (; j + 16 <= end; j += 16) {
        uint2 e[4];
#pragma unroll
        for (int k = 0; k < 4; k++) e[k] = ed[j + k * 4 + grp];
        float2 f[4];
#pragma unroll
        for (int k = 0; k < 4; k++) {
            __nv_bfloat162 v = *reinterpret_cast<const __nv_bfloat162*>(
                xb + (size_t)e[k].x * 16 + sub * 2);
            f[k] = __bfloat1622float2(v);
        }
#pragma unroll
        for (int k = 0; k < 4; k++) {
            float w = __uint_as_float(e[k].y);
            ax = fmaf(w, f[k].x, ax);
            ay = fmaf(w, f[k].y, ay);
        }
    }
    for (; j < end; j += 4) {
        int idx = j + grp;
        if (idx < end) {
            uint2 e = ed[idx];
            __nv_bfloat162 v = *reinterpret_cast<const __nv_bfloat162*>(
                xb + (size_t)e.x * 16 + sub * 2);
            float2 f = __bfloat1622float2(v);
            float w = __uint_as_float(e.y);
            ax = fmaf(w, f.x, ax); ay = fmaf(w, f.y, ay);
        }
    }
    ax += __shfl_xor_sync(0xffffffffu, ax, 8);
    ay += __shfl_xor_sync(0xffffffffu, ay, 8);
    ax += __shfl_xor_sync(0xffffffffu, ax, 16);
    ay += __shfl_xor_sync(0xffffffffu, ay, 16);
    if (lane < 8) {
        float di = dis[warp];
        float2 r; r.x = -di * ax; r.y = -di * ay;
        *reinterpret_cast<float2*>(out + (size_t)warp * 16 + sub * 2) = r;
        if (WRITE_B) {
            float2 s; s.x = di * r.x; s.y = di * r.y;
            __nv_bfloat162 b = __float22bfloat162_rn(s);
            *reinterpret_cast<__nv_bfloat162*>(outb + (size_t)warp * 16 + sub * 2) = b;
        }
    }
}

// ---------------------------------------------------------------------------
// bf16 CSR gather, C == 32: warp per node, 16 edges / iteration.
// grp = lane>>4 (2 edge slots), sub = lane&15 (bf162 channel pair).
// ---------------------------------------------------------------------------
template <bool WRITE_B>
__global__ void prop_c32_bf16(const __nv_bfloat16* __restrict__ xb,
                              const float* __restrict__ dis,
                              const uint2* __restrict__ ed, const int* __restrict__ rs,
                              float* __restrict__ out, __nv_bfloat16* __restrict__ outb,
                              int N) {
    int warp = (blockIdx.x * blockDim.x + threadIdx.x) >> 5;
    int lane = threadIdx.x & 31;
    if (warp >= N) return;
    int grp = lane >> 4;
    int sub = lane & 15;
    int beg = rs[warp], end = rs[warp + 1];
    float ax = 0.f, ay = 0.f;
    int j = beg;
    for (; j + 16 <= end; j += 16) {
        uint2 e[8];
#pragma unroll
        for (int k = 0; k < 8; k++) e[k] = ed[j + k * 2 + grp];
        float2 f[8];
#pragma unroll
        for (int k = 0; k < 8; k++) {
            __nv_bfloat162 v = *reinterpret_cast<const __nv_bfloat162*>(
                xb + (size_t)e[k].x * 32 + sub * 2);
            f[k] = __bfloat1622float2(v);
        }
#pragma unroll
        for (int k = 0; k < 8; k++) {
            float w = __uint_as_float(e[k].y);
            ax = fmaf(w, f[k].x, ax);
            ay = fmaf(w, f[k].y, ay);
        }
    }
    for (; j < end; j += 2) {
        int idx = j + grp;
        if (idx < end) {
            uint2 e = ed[idx];
            __nv_bfloat162 v = *reinterpret_cast<const __nv_bfloat162*>(
                xb + (size_t)e.x * 32 + sub * 2);
            float2 f = __bfloat1622float2(v);
            float w = __uint_as_float(e.y);
            ax = fmaf(w, f.x, ax); ay = fmaf(w, f.y, ay);
        }
    }
    ax += __shfl_xor_sync(0xffffffffu, ax, 16);
    ay += __shfl_xor_sync(0xffffffffu, ay, 16);
    if (lane < 16) {
        float di = dis[warp];
        float2 r; r.x = -di * ax; r.y = -di * ay;
        *reinterpret_cast<float2*>(out + (size_t)warp * 32 + sub * 2) = r;
        if (WRITE_B) {
            float2 s; s.x = di * r.x; s.y = di * r.y;
            __nv_bfloat162 b = __float22bfloat162_rn(s);
            *reinterpret_cast<__nv_bfloat162*>(outb + (size_t)warp * 32 + sub * 2) = b;
        }
    }
}

// ---------------------------------------------------------------------------
// C == 4 prop of zpack (dis-scaled [z1|z2]).
// out c in {0,1}: -dis[d]*acc (true P z1); c in {2,3}: -dis[d]^2*acc (scaled P z2).
// ---------------------------------------------------------------------------
__global__ void prop_csr_c4(const float* __restrict__ zs, const float* __restrict__ dis,
                            const uint2* __restrict__ ed, const int* __restrict__ rs,
                            float* __restrict__ out, int N) {
    int warp = (blockIdx.x * blockDim.x + threadIdx.x) >> 5;
    int lane = threadIdx.x & 31;
    if (warp >= N) return;
    int k = lane >> 2;
    int c = lane & 3;
    int beg = rs[warp], end = rs[warp + 1];
    float acc = 0.f;
    for (int j = beg + k; j < end; j += 8) {
        uint2 e = ed[j];
        acc = fmaf(__uint_as_float(e.y), __ldg(zs + (size_t)e.x * 4 + c), acc);
    }
#pragma unroll
    for (int off = 16; off >= 4; off >>= 1)
        acc += __shfl_down_sync(0xffffffffu, acc, off);
    if (lane < 4) {
        float di = dis[warp];
        float r = -di * acc;
        out[(size_t)warp * 4 + c] = (c < 2) ? r : di * r;
    }
}

// ---------------------------------------------------------------------------
// Final tail: y = part + t4[:,0:2] + 2 * (-dis[d] * sum ea * t4s[s, 2+c])
// ---------------------------------------------------------------------------
__global__ void prop2_final_k(const float* __restrict__ t4, const float* __restrict__ part,
                              const float* __restrict__ dis,
                              const uint2* __restrict__ ed, const int* __restrict__ rs,
                              float* __restrict__ y, int N) {
    int warp = (blockIdx.x * blockDim.x + threadIdx.x) >> 5;
    int lane = threadIdx.x & 31;
    if (warp >= N) return;
    int k = lane >> 1;
    int c = lane & 1;
    int beg = rs[warp], end = rs[warp + 1];
    float acc = 0.f;
    for (int j = beg + k; j < end; j += 16) {
        uint2 e = ed[j];
        acc = fmaf(__uint_as_float(e.y), __ldg(t4 + (size_t)e.x * 4 + 2 + c), acc);
    }
#pragma unroll
    for (int off = 16; off >= 2; off >>= 1)
        acc += __shfl_down_sync(0xffffffffu, acc, off);
    if (lane < 2) {
        float w = -dis[warp] * acc;
        y[(size_t)warp * 2 + c] = part[(size_t)warp * 2 + c]
                                + t4[(size_t)warp * 4 + c] + 2.f * w;
    }
}

// ---------------------------------------------------------------------------
// Layer-4 head GEMM: part = h@W0 - h@W2 ; zpack = dis[n]*[h@W1 | h@W2]
// ---------------------------------------------------------------------------
__global__ void gemm_head_64_2(const float* __restrict__ h, const float* __restrict__ dis,
                               const float* __restrict__ W,
                               float* __restrict__ part, float* __restrict__ zpack, int n) {
    __shared__ float sW[6 * 64];
    for (int i = threadIdx.x; i < 384; i += blockDim.x) {
        int k = i / 128, rem = i % 128, ci = rem / 2, co = rem % 2;
        sW[(k * 2 + co) * 64 + ci] = W[i];
    }
    __syncthreads();
    int warp = (blockIdx.x * blockDim.x + threadIdx.x) >> 5;
    int lane = threadIdx.x & 31;
    if (warp >= n) return;
    size_t base = (size_t)warp * 64;
    float a0 = h[base + lane];
    float a1 = h[base + lane + 32];
    float r[6];
#pragma unroll
    for (int m = 0; m < 6; m++) {
        const float* w = sW + m * 64;
        float acc = fmaf(a1, w[lane + 32], a0 * w[lane]);
#pragma unroll
        for (int off = 16; off > 0; off >>= 1)
            acc += __shfl_down_sync(0xffffffffu, acc, off);
        r[m] = acc;
    }
    if (lane == 0) {
        float di = dis[warp];
        part[(size_t)warp * 2 + 0] = r[0] - r[4];
        part[(size_t)warp * 2 + 1] = r[1] - r[5];
        float4 z; z.x = di * r[2]; z.y = di * r[3]; z.z = di * r[4]; z.w = di * r[5];
        *reinterpret_cast<float4*>(zpack + (size_t)warp * 4) = z;
    }
}

// ---------------------------------------------------------------------------
// Combine 1->16: emits fp32 out and dis-scaled bf16 shadow
// ---------------------------------------------------------------------------
__global__ void combine_1_16(const float* __restrict__ f0, const float* __restrict__ t1,
                             const float* __restrict__ t2, const float* __restrict__ dis,
                             const float* __restrict__ W,
                             float* __restrict__ out, __nv_bfloat16* __restrict__ outb,
                             int n) {
    __shared__ float sW[48];
    if (threadIdx.x < 48) sW[threadIdx.x] = W[threadIdx.x];
    __syncthreads();
    int tid = blockIdx.x * blockDim.x + threadIdx.x;
    int node = tid >> 4;
    int co = tid & 15;
    if (node >= n) return;
    float a = f0[node];
    float b = t1[node];
    float d = 2.f * t2[node] - a;
    float acc = a * sW[co] + b * sW[16 + co] + d * sW[32 + co];
    float r = fmaxf(acc, 0.f);
    out[(size_t)node * 16 + co] = r;
    outb[(size_t)node * 16 + co] = __float2bfloat16_rn(dis[node] * r);
}

// ---------------------------------------------------------------------------
// Combine 16->32: warp per node; emits dis-scaled bf16 shadow
// ---------------------------------------------------------------------------
__global__ void combine_16_32(const float* __restrict__ f0, const float* __restrict__ t1,
                              const float* __restrict__ t2, const float* __restrict__ dis,
                              const float* __restrict__ W,
                              float* __restrict__ out, __nv_bfloat16* __restrict__ outb,
                              int n) {
    __shared__ float sW[3 * 16 * 32];
    for (int i = threadIdx.x; i < 3 * 16 * 32; i += blockDim.x) sW[i] = W[i];
    __syncthreads();
    int warp = (blockIdx.x * blockDim.x + threadIdx.x) >> 5;
    int lane = threadIdx.x & 31;
    if (warp >= n) return;
    int c = lane & 15;
    float a = f0[(size_t)warp * 16 + c];
    float b = t1[(size_t)warp * 16 + c];
    float d = 2.f * t2[(size_t)warp * 16 + c] - a;
    float acc = 0.f;
#pragma unroll
    for (int cc = 0; cc < 16; cc++) {
        float av = __shfl_sync(0xffffffffu, a, cc);
        float bv = __shfl_sync(0xffffffffu, b, cc);
        float dv = __shfl_sync(0xffffffffu, d, cc);
        acc = fmaf(av, sW[cc * 32 + lane], acc);
        acc = fmaf(bv, sW[512 + cc * 32 + lane], acc);
        acc = fmaf(dv, sW[1024 + cc * 32 + lane], acc);
    }
    float r = fmaxf(acc, 0.f);
    out[(size_t)warp * 32 + lane] = r;
    outb[(size_t)warp * 32 + lane] = __float2bfloat16_rn(dis[warp] * r);
}

// ---------------------------------------------------------------------------
// Combine 32->64: warp per node (fp32 only)
// ---------------------------------------------------------------------------
__global__ void combine_32_64(const float* __restrict__ f0, const float* __restrict__ t1,
                              const float* __restrict__ t2, const float* __restrict__ W,
                              float* __restrict__ out, int n) {
    __shared__ float sW[3 * 32 * 64];
    for (int i = threadIdx.x; i < 3 * 32 * 64; i += blockDim.x) sW[i] = W[i];
    __syncthreads();
    int warp = (blockIdx.x * blockDim.x + threadIdx.x) >> 5;
    int lane = threadIdx.x & 31;
    if (warp >= n) return;
    float a = f0[(size_t)warp * 32 + lane];
    float b = t1[(size_t)warp * 32 + lane];
    float d = 2.f * t2[(size_t)warp * 32 + lane] - a;
    float acc0 = 0.f, acc1 = 0.f;
#pragma unroll
    for (int cc = 0; cc < 32; cc++) {
        float av = __shfl_sync(0xffffffffu, a, cc);
        float bv = __shfl_sync(0xffffffffu, b, cc);
        float dv = __shfl_sync(0xffffffffu, d, cc);
        const float* w0 = sW + cc * 64;
        const float* w1 = sW + 2048 + cc * 64;
        const float* w2 = sW + 4096 + cc * 64;
        acc0 = fmaf(av, w0[lane], acc0);
        acc0 = fmaf(bv, w1[lane], acc0);
        acc0 = fmaf(dv, w2[lane], acc0);
        acc1 = fmaf(av, w0[lane + 32], acc1);
        acc1 = fmaf(bv, w1[lane + 32], acc1);
        acc1 = fmaf(dv, w2[lane + 32], acc1);
    }
    out[(size_t)warp * 64 + lane] = fmaxf(acc0, 0.f);
    out[(size_t)warp * 64 + lane + 32] = fmaxf(acc1, 0.f);
}

extern "C" void kernel_launch(void* const* d_in, const int* in_sizes, int n_in,
                              void* d_out, int out_size) {
    const float* x = (const float*)d_in[0];
    const int* edge_index = (const int*)d_in[1];
    const float* ea = (const float*)d_in[2];
    const float* W1 = (const float*)d_in[3];
    const float* W2 = (const float*)d_in[4];
    const float* W3 = (const float*)d_in[5];
    const float* W4 = (const float*)d_in[6];

    const int N = in_sizes[0];
    const int E = in_sizes[2];
    const int* src = edge_index;
    const int* dst = edge_index + E;

    float *deg, *dis, *xs, *bufA, *bufB, *t1, *t1s, *t2;
    int *cnt, *rs, *cur, *bsum;
    uint2* edges;
    __nv_bfloat16 *xb, *tb;
    cudaGetSymbolAddress((void**)&deg, g_deg);
    cudaGetSymbolAddress((void**)&dis, g_dis);
    cudaGetSymbolAddress((void**)&xs, g_xs);
    cudaGetSymbolAddress((void**)&cnt, g_cnt);
    cudaGetSymbolAddress((void**)&rs, g_rs);
    cudaGetSymbolAddress((void**)&cur, g_cur);
    cudaGetSymbolAddress((void**)&bsum, g_bsum);
    cudaGetSymbolAddress((void**)&edges, g_edges);
    cudaGetSymbolAddress((void**)&bufA, g_bufA);
    cudaGetSymbolAddress((void**)&bufB, g_bufB);
    cudaGetSymbolAddress((void**)&t1, g_t1);
    cudaGetSymbolAddress((void**)&t1s, g_t1s);
    cudaGetSymbolAddress((void**)&t2, g_t2);
    cudaGetSymbolAddress((void**)&xb, g_xb);
    cudaGetSymbolAddress((void**)&tb, g_tb);

    // ---- build CSR (records need only src/ea) + dis ----
    zero_build_k<<<cdiv(N, 256), 256>>>(deg, cnt, N);
    deg_hist_k<<<cdiv(E, 256), 256>>>(src, dst, ea, deg, cnt, E);
    int nb = cdiv(N, SCAN_ELEMS);
    bsum_k<<<nb, SCAN_TPB>>>(cnt, bsum, N);
    bscan_k<<<1, 128>>>(bsum, nb, rs + N);
    expand_k<<<nb, SCAN_TPB>>>(cnt, bsum, rs, cur, N);
    scatter_k<<<cdiv(E, 256), 256>>>(src, dst, ea, cur, edges, E);
    dis_k<<<cdiv(N, 256), 256>>>(deg, x, dis, xs, N);

    const int WPB = 256;
    int grid_n = cdiv((long long)N * 32, WPB);

    // ---- layer 1: 1 -> 16, relu ----
    prop_c1<true><<<grid_n, WPB>>>(xs, dis, edges, rs, t1, t1s, N);
    prop_c1<false><<<grid_n, WPB>>>(t1s, dis, edges, rs, t2, nullptr, N);
    combine_1_16<<<cdiv((long long)N * 16, 256), 256>>>(x, t1, t2, dis, W1, bufA, xb, N);

    // ---- layer 2: 16 -> 32, relu (bf16 gathers) ----
    prop_c16_bf16<true><<<grid_n, WPB>>>(xb, dis, edges, rs, t1, tb, N);
    prop_c16_bf16<false><<<grid_n, WPB>>>(tb, dis, edges, rs, t2, nullptr, N);
    combine_16_32<<<grid_n, WPB>>>(bufA, t1, t2, dis, W2, bufB, xb, N);

    // ---- layer 3: 32 -> 64, relu (bf16 gathers) ----
    prop_c32_bf16<true><<<grid_n, WPB>>>(xb, dis, edges, rs, t1, tb, N);
    prop_c32_bf16<false><<<grid_n, WPB>>>(tb, dis, edges, rs, t2, nullptr, N);
    combine_32_64<<<grid_n, WPB>>>(bufB, t1, t2, W3, bufA, N);

    // ---- layer 4: 64 -> 2 via project-then-propagate ----
    gemm_head_64_2<<<grid_n, WPB>>>(bufA, dis, W4, bufB, t1, N);
    prop_csr_c4<<<grid_n, WPB>>>(t1, dis, edges, rs, t2, N);
    prop2_final_k<<<grid_n, WPB>>>(t2, bufB, dis, edges, rs, (float*)d_out, N);
}